// round 1
// baseline (speedup 1.0000x reference)
#include <cuda_runtime.h>

#define Bn      16
#define Cn      512
#define HWn     32
#define Sn      1024
#define GROUPSn 32
#define CPGn    16

// Scratch (no allocations allowed) — ~128 MB of __device__ globals.
__device__ float g_hn[Bn * Cn * Sn];   // groupnormed x, [b, c, s]
__device__ float g_Q [Bn * Sn * Cn];   // [b, s, o]  (spatial-major for Gram reads)
__device__ float g_K [Bn * Sn * Cn];   // [b, s, o]
__device__ float g_V [Bn * Cn * Sn];   // [b, o, s]
__device__ float g_D [Bn * Sn];        // diag softmax values, [b, h*32+w]

// ---------------------------------------------------------------------------
// Kernel 1: GroupNorm. One block per (b, group); 16 ch x 1024 = 16384 floats.
// ---------------------------------------------------------------------------
__global__ void __launch_bounds__(256) groupnorm_kernel(const float* __restrict__ x) {
    int b = blockIdx.x / GROUPSn;
    int g = blockIdx.x % GROUPSn;
    size_t base = ((size_t)b * Cn + g * CPGn) * Sn;
    const float4* x4 = (const float4*)(x + base);
    float4*       h4 = (float4*)(g_hn + base);
    int tid = threadIdx.x;
    const int N4 = CPGn * Sn / 4;  // 4096

    float s = 0.f, ss = 0.f;
    for (int i = tid; i < N4; i += 256) {
        float4 v = x4[i];
        s  += v.x + v.y + v.z + v.w;
        ss += v.x * v.x + v.y * v.y + v.z * v.z + v.w * v.w;
    }
    __shared__ float rs[256], rq[256];
    rs[tid] = s; rq[tid] = ss;
    __syncthreads();
    for (int off = 128; off; off >>= 1) {
        if (tid < off) { rs[tid] += rs[tid + off]; rq[tid] += rq[tid + off]; }
        __syncthreads();
    }
    const float invN = 1.f / (CPGn * Sn);
    float mean = rs[0] * invN;
    float var  = rq[0] * invN - mean * mean;
    float inv  = rsqrtf(var + 1e-5f);

    for (int i = tid; i < N4; i += 256) {
        float4 v = x4[i];
        float4 o;
        o.x = (v.x - mean) * inv; o.y = (v.y - mean) * inv;
        o.z = (v.z - mean) * inv; o.w = (v.w - mean) * inv;
        h4[i] = o;
    }
}

// ---------------------------------------------------------------------------
// Kernel 2: projection GEMM, spatial-major store (for Q, K).
// out[b, s, o] = sum_c g_hn[b, c, s] * W[c, o] + bias[o]
// 64x64 tile, kc=16, 256 threads, 4x4 register micro-tile.
// ---------------------------------------------------------------------------
__global__ void __launch_bounds__(256) gemm_sn_kernel(const float* __restrict__ W,
                                                      const float* __restrict__ bias,
                                                      float* __restrict__ out) {
    int b  = blockIdx.z;
    int s0 = blockIdx.x * 64;
    int o0 = blockIdx.y * 64;
    const float* X = g_hn + (size_t)b * Cn * Sn;

    __shared__ float As[16][64];  // As[k][m] = X[(c0+k)*S + s0+m]
    __shared__ float Bs[16][64];  // Bs[k][n] = W[(c0+k)*C + o0+n]

    int tid = threadIdx.x;
    int lr = tid >> 4;            // 0..15 (k row for loads)
    int lc = (tid & 15) * 4;      // 0..60
    int ty = tid >> 4, tx = tid & 15;

    float acc[4][4] = {};
    for (int c0 = 0; c0 < Cn; c0 += 16) {
        float4 a = *(const float4*)(X + (size_t)(c0 + lr) * Sn + s0 + lc);
        float4 w = *(const float4*)(W + (size_t)(c0 + lr) * Cn + o0 + lc);
        *(float4*)&As[lr][lc] = a;
        *(float4*)&Bs[lr][lc] = w;
        __syncthreads();
#pragma unroll
        for (int k = 0; k < 16; k++) {
            float4 av = *(const float4*)&As[k][ty * 4];
            float4 bv = *(const float4*)&Bs[k][tx * 4];
            float aa[4] = {av.x, av.y, av.z, av.w};
            float bb[4] = {bv.x, bv.y, bv.z, bv.w};
#pragma unroll
            for (int i2 = 0; i2 < 4; i2++)
#pragma unroll
                for (int j2 = 0; j2 < 4; j2++)
                    acc[i2][j2] += aa[i2] * bb[j2];
        }
        __syncthreads();
    }
    float bv4[4];
#pragma unroll
    for (int j2 = 0; j2 < 4; j2++) bv4[j2] = bias[o0 + tx * 4 + j2];
    float* ob = out + (size_t)b * Sn * Cn;
#pragma unroll
    for (int i2 = 0; i2 < 4; i2++) {
        size_t row = (size_t)(s0 + ty * 4 + i2) * Cn + o0 + tx * 4;
        float4 st = {acc[i2][0] + bv4[0], acc[i2][1] + bv4[1],
                     acc[i2][2] + bv4[2], acc[i2][3] + bv4[3]};
        *(float4*)(ob + row) = st;
    }
}

// ---------------------------------------------------------------------------
// Kernel 3: projection GEMM, channel-major store (for V and the final fused).
// out[b, o, s] = sum_c X[b, c, s] * W[c, o]   (+ epilogue)
// use_d==0:  out = acc + bias[o]
// use_d==1:  out = xres + g_D[b, s] * acc + bias[o]   (residual + diag scale)
// ---------------------------------------------------------------------------
__global__ void __launch_bounds__(256) gemm_ns_kernel(const float* __restrict__ W,
                                                      const float* __restrict__ bias,
                                                      const float* __restrict__ X,
                                                      float* __restrict__ out,
                                                      const float* __restrict__ xres,
                                                      int use_d) {
    int b  = blockIdx.z;
    int s0 = blockIdx.x * 64;
    int o0 = blockIdx.y * 64;
    const float* Xb = X + (size_t)b * Cn * Sn;

    __shared__ float As[16][64];  // As[k][m] = W[(c0+k)*C + o0+m]  (m = o)
    __shared__ float Bs[16][64];  // Bs[k][n] = Xb[(c0+k)*S + s0+n] (n = s)

    int tid = threadIdx.x;
    int lr = tid >> 4;
    int lc = (tid & 15) * 4;
    int ty = tid >> 4, tx = tid & 15;

    float acc[4][4] = {};
    for (int c0 = 0; c0 < Cn; c0 += 16) {
        float4 w  = *(const float4*)(W  + (size_t)(c0 + lr) * Cn + o0 + lc);
        float4 xv = *(const float4*)(Xb + (size_t)(c0 + lr) * Sn + s0 + lc);
        *(float4*)&As[lr][lc] = w;
        *(float4*)&Bs[lr][lc] = xv;
        __syncthreads();
#pragma unroll
        for (int k = 0; k < 16; k++) {
            float4 av = *(const float4*)&As[k][ty * 4];
            float4 bv = *(const float4*)&Bs[k][tx * 4];
            float aa[4] = {av.x, av.y, av.z, av.w};
            float bb[4] = {bv.x, bv.y, bv.z, bv.w};
#pragma unroll
            for (int i2 = 0; i2 < 4; i2++)
#pragma unroll
                for (int j2 = 0; j2 < 4; j2++)
                    acc[i2][j2] += aa[i2] * bb[j2];
        }
        __syncthreads();
    }

    size_t bbase = (size_t)b * Cn * Sn;
    if (use_d) {
        float dv[4];
#pragma unroll
        for (int j2 = 0; j2 < 4; j2++) dv[j2] = g_D[b * Sn + s0 + tx * 4 + j2];
#pragma unroll
        for (int i2 = 0; i2 < 4; i2++) {
            float bb = bias[o0 + ty * 4 + i2];
            size_t idx = bbase + (size_t)(o0 + ty * 4 + i2) * Sn + s0 + tx * 4;
            float4 xr = *(const float4*)(xres + idx);
            float4 st = {xr.x + dv[0] * acc[i2][0] + bb,
                         xr.y + dv[1] * acc[i2][1] + bb,
                         xr.z + dv[2] * acc[i2][2] + bb,
                         xr.w + dv[3] * acc[i2][3] + bb};
            *(float4*)(out + idx) = st;
        }
    } else {
#pragma unroll
        for (int i2 = 0; i2 < 4; i2++) {
            float bb = bias[o0 + ty * 4 + i2];
            size_t idx = bbase + (size_t)(o0 + ty * 4 + i2) * Sn + s0 + tx * 4;
            float4 st = {acc[i2][0] + bb, acc[i2][1] + bb,
                         acc[i2][2] + bb, acc[i2][3] + bb};
            *(float4*)(out + idx) = st;
        }
    }
}

// ---------------------------------------------------------------------------
// Kernel 4: scores + diag softmax.
// Block = (b, i, 4 consecutive j). Computes the 32 x (4*32) score tile
//   sc[h][jj*32+H] = scale * <Q[b, h*32+i, :], K[b, H*32+(j0+jj), :]>
// then 4 independent softmaxes over their 1024 entries; only the diag value
//   exp(sc[i][jj*32 + j]) / sum  is kept -> g_D[b, i*32 + j].
// ---------------------------------------------------------------------------
__global__ void __launch_bounds__(256) scores_kernel() {
    int b  = blockIdx.z;
    int i  = blockIdx.y;       // 0..31
    int j0 = blockIdx.x * 4;   // 0,4,...,28
    const float* Qb = g_Q + (size_t)b * Sn * Cn;
    const float* Kb = g_K + (size_t)b * Sn * Cn;

    __shared__ float Qs[16][33];    // Qs[k][h]
    __shared__ float Ks[16][132];   // Ks[k][n], n = jj*32 + H
    __shared__ float sc[32][132];
    __shared__ float red[256];

    int tid = threadIdx.x;
    int ty = tid >> 5;   // 0..7  -> rows h = ty*4 + a
    int tx = tid & 31;   // 0..31 -> cols n = tx*4 + c

    float acc[4][4] = {};
    for (int c0 = 0; c0 < Cn; c0 += 16) {
        if (tid < 128) {
            int n = tid >> 2;          // h index 0..31
            int f = (tid & 3) * 4;     // c offset 0..12
            float4 q = *(const float4*)(Qb + (size_t)(n * 32 + i) * Cn + c0 + f);
            Qs[f + 0][n] = q.x; Qs[f + 1][n] = q.y;
            Qs[f + 2][n] = q.z; Qs[f + 3][n] = q.w;
        }
#pragma unroll
        for (int it = 0; it < 2; it++) {
            int id = tid + it * 256;
            int n  = id >> 2;          // 0..127
            int f  = (id & 3) * 4;
            int jj = n >> 5;
            int Hh = n & 31;
            float4 kv = *(const float4*)(Kb + (size_t)(Hh * 32 + j0 + jj) * Cn + c0 + f);
            Ks[f + 0][n] = kv.x; Ks[f + 1][n] = kv.y;
            Ks[f + 2][n] = kv.z; Ks[f + 3][n] = kv.w;
        }
        __syncthreads();
#pragma unroll
        for (int k = 0; k < 16; k++) {
            float qv[4], kv[4];
#pragma unroll
            for (int u = 0; u < 4; u++) qv[u] = Qs[k][ty * 4 + u];
#pragma unroll
            for (int u = 0; u < 4; u++) kv[u] = Ks[k][tx * 4 + u];
#pragma unroll
            for (int a = 0; a < 4; a++)
#pragma unroll
                for (int c = 0; c < 4; c++)
                    acc[a][c] += qv[a] * kv[c];
        }
        __syncthreads();
    }

    const float scale = 0.04419417382415922f;  // 512^-0.5
#pragma unroll
    for (int a = 0; a < 4; a++)
#pragma unroll
        for (int c = 0; c < 4; c++) {
            acc[a][c] *= scale;
            sc[ty * 4 + a][tx * 4 + c] = acc[a][c];
        }
    __syncthreads();

    for (int jj = 0; jj < 4; jj++) {
        float lm = -1e30f;
        for (int l = tid; l < 1024; l += 256) {
            int h = l >> 5, H = l & 31;
            lm = fmaxf(lm, sc[h][jj * 32 + H]);
        }
        red[tid] = lm; __syncthreads();
        for (int off = 128; off; off >>= 1) {
            if (tid < off) red[tid] = fmaxf(red[tid], red[tid + off]);
            __syncthreads();
        }
        float mx = red[0];
        __syncthreads();

        float ls = 0.f;
        for (int l = tid; l < 1024; l += 256) {
            int h = l >> 5, H = l & 31;
            ls += __expf(sc[h][jj * 32 + H] - mx);
        }
        red[tid] = ls; __syncthreads();
        for (int off = 128; off; off >>= 1) {
            if (tid < off) red[tid] += red[tid + off];
            __syncthreads();
        }
        if (tid == 0) {
            int j = j0 + jj;
            float numer = __expf(sc[i][jj * 32 + j] - mx);
            g_D[b * Sn + i * 32 + j] = numer / red[0];
        }
        __syncthreads();
    }
}

// ---------------------------------------------------------------------------
extern "C" void kernel_launch(void* const* d_in, const int* in_sizes, int n_in,
                              void* d_out, int out_size) {
    const float* x  = (const float*)d_in[0];
    const float* Wq = (const float*)d_in[1];
    const float* bq = (const float*)d_in[2];
    const float* Wk = (const float*)d_in[3];
    const float* bk = (const float*)d_in[4];
    const float* Wv = (const float*)d_in[5];
    const float* bv = (const float*)d_in[6];
    const float* Wn = (const float*)d_in[7];
    const float* bn = (const float*)d_in[8];
    float* out = (float*)d_out;

    float *pQ, *pK, *pV, *pH;
    cudaGetSymbolAddress((void**)&pQ, g_Q);
    cudaGetSymbolAddress((void**)&pK, g_K);
    cudaGetSymbolAddress((void**)&pV, g_V);
    cudaGetSymbolAddress((void**)&pH, g_hn);

    groupnorm_kernel<<<Bn * GROUPSn, 256>>>(x);

    dim3 gP(Sn / 64, Cn / 64, Bn);  // (16, 8, 16)
    gemm_sn_kernel<<<gP, 256>>>(Wq, bq, pQ);
    gemm_sn_kernel<<<gP, 256>>>(Wk, bk, pK);
    gemm_ns_kernel<<<gP, 256>>>(Wv, bv, pH, pV, nullptr, 0);

    scores_kernel<<<dim3(8, 32, Bn), 256>>>();

    gemm_ns_kernel<<<gP, 256>>>(Wn, bn, pV, out, x, 1);
}

// round 5
// speedup vs baseline: 4.4520x; 4.4520x over previous
#include <cuda_runtime.h>
#include <cuda_bf16.h>

#define Bn 16
#define Cn 512
#define Sn 1024

// ---- scratch (no allocs allowed) ----
__device__ __nv_bfloat16 g_hn [Bn * Cn * Sn];   // [b][c][s]  (k-major for proj A)
__device__ __nv_bfloat16 g_Qt [Bn * Sn * Cn];   // [b][s][o]
__device__ __nv_bfloat16 g_Kt [Bn * Sn * Cn];   // [b][s][o]
__device__ __nv_bfloat16 g_Vt [Bn * Sn * Cn];   // [b][s][o]
__device__ __nv_bfloat16 g_Wqt[Cn * Cn];        // W^T : [out][in] bf16
__device__ __nv_bfloat16 g_Wkt[Cn * Cn];
__device__ __nv_bfloat16 g_Wvt[Cn * Cn];
__device__ __nv_bfloat16 g_Wnt[Cn * Cn];
__device__ float         g_D  [Bn * Sn];        // diag softmax

// ---------------------------------------------------------------------------
__device__ __forceinline__ void mma_bf16(float c[4], const unsigned a[4],
                                         unsigned b0, unsigned b1) {
    asm volatile(
        "mma.sync.aligned.m16n8k16.row.col.f32.bf16.bf16.f32 "
        "{%0,%1,%2,%3},{%4,%5,%6,%7},{%8,%9},{%0,%1,%2,%3};\n"
        : "+f"(c[0]), "+f"(c[1]), "+f"(c[2]), "+f"(c[3])
        : "r"(a[0]), "r"(a[1]), "r"(a[2]), "r"(a[3]), "r"(b0), "r"(b1));
}

// ---------------------------------------------------------------------------
// Weight transpose+convert: Wt[out][in] bf16 = W[in][out] fp32.
// ---------------------------------------------------------------------------
__global__ void __launch_bounds__(256) wconv_kernel(const float* __restrict__ Wq,
                                                    const float* __restrict__ Wk,
                                                    const float* __restrict__ Wv,
                                                    const float* __restrict__ Wn) {
    __shared__ float t[32][33];
    int w = blockIdx.z;
    const float* src = (w == 0) ? Wq : (w == 1) ? Wk : (w == 2) ? Wv : Wn;
    __nv_bfloat16* dst = (w == 0) ? g_Wqt : (w == 1) ? g_Wkt : (w == 2) ? g_Wvt : g_Wnt;
    int c0 = blockIdx.x * 32, r0 = blockIdx.y * 32;
    int tx = threadIdx.x & 31, ty = threadIdx.x >> 5;
#pragma unroll
    for (int i = 0; i < 4; i++)
        t[ty + i * 8][tx] = src[(size_t)(r0 + ty + i * 8) * Cn + c0 + tx];
    __syncthreads();
#pragma unroll
    for (int i = 0; i < 4; i++)
        dst[(size_t)(c0 + ty + i * 8) * Cn + r0 + tx] = __float2bfloat16(t[tx][ty + i * 8]);
}

// ---------------------------------------------------------------------------
// GroupNorm: one block per (b, group). Whole group tile kept in registers.
// Writes bf16 hn[c][s].
// ---------------------------------------------------------------------------
__global__ void __launch_bounds__(256) gn_kernel(const float* __restrict__ x) {
    int b = blockIdx.x >> 5, g = blockIdx.x & 31;
    size_t base = ((size_t)b * Cn + g * 16) * Sn;
    const float4* x4 = (const float4*)(x + base);
    int tid = threadIdx.x;

    float4 v[16];
    float s = 0.f, ss = 0.f;
#pragma unroll
    for (int i = 0; i < 16; i++) {
        v[i] = x4[tid + i * 256];
        s  += v[i].x + v[i].y + v[i].z + v[i].w;
        ss += v[i].x * v[i].x + v[i].y * v[i].y + v[i].z * v[i].z + v[i].w * v[i].w;
    }
    __shared__ float rs[256], rq[256];
    rs[tid] = s; rq[tid] = ss;
    __syncthreads();
    for (int off = 128; off; off >>= 1) {
        if (tid < off) { rs[tid] += rs[tid + off]; rq[tid] += rq[tid + off]; }
        __syncthreads();
    }
    const float invN = 1.f / 16384.f;
    float mean = rs[0] * invN;
    float var  = rq[0] * invN - mean * mean;
    float inv  = rsqrtf(var + 1e-5f);

    uint2* h2 = (uint2*)(g_hn + base);
#pragma unroll
    for (int i = 0; i < 16; i++) {
        __nv_bfloat162 p0 = __floats2bfloat162_rn((v[i].x - mean) * inv, (v[i].y - mean) * inv);
        __nv_bfloat162 p1 = __floats2bfloat162_rn((v[i].z - mean) * inv, (v[i].w - mean) * inv);
        uint2 u; u.x = *(unsigned*)&p0; u.y = *(unsigned*)&p1;
        h2[tid + i * 256] = u;
    }
}

// ---------------------------------------------------------------------------
// Projection GEMM (Q/K/V): out[b][s][o] = sum_c hn[b][c][s] * W[c][o] + bias[o]
// A = hn (k-major [c][s]) via ldmatrix.trans;  B = Wt[o][c] via direct LDS.
// Block 128(m=s) x 64(n=o), BK=32, 8 warps (4x2), warp tile 32x32.
// ---------------------------------------------------------------------------
__global__ void __launch_bounds__(256) proj_kernel(const __nv_bfloat16* __restrict__ Wt,
                                                   const float* __restrict__ bias,
                                                   __nv_bfloat16* __restrict__ out) {
    int b = blockIdx.z, s0 = blockIdx.x * 128, o0 = blockIdx.y * 64;
    const __nv_bfloat16* A = g_hn + (size_t)b * Cn * Sn;

    __shared__ __align__(16) __nv_bfloat16 As[32][136];  // [k][m]
    __shared__ __align__(16) __nv_bfloat16 Bs[64][40];   // [n][k]

    int tid = threadIdx.x, lane = tid & 31, warp = tid >> 5;
    int wm = (warp & 3) * 32, wn = (warp >> 2) * 32;
    int g = lane >> 2, t = lane & 3;

    int ra = tid >> 3, ca = (tid & 7) * 16;  // As loader
    int rb = tid >> 2, cb = (tid & 3) * 8;   // Bs loader

    // ldmatrix.x4.trans lane addressing for A (k-major storage)
    int mi = lane >> 3;
    int a_kr = (lane & 7) + ((mi >> 1) << 3);
    int a_mc = (mi & 1) << 3;

    uint4 pa0, pa1, pb;
    pa0 = *(const uint4*)(A + (size_t)ra * Sn + s0 + ca);
    pa1 = *(const uint4*)(A + (size_t)ra * Sn + s0 + ca + 8);
    pb  = *(const uint4*)(Wt + (size_t)(o0 + rb) * Cn + cb);

    float acc[2][4][4] = {};
    for (int c0 = 0; c0 < Cn; c0 += 32) {
        *(uint4*)&As[ra][ca]     = pa0;
        *(uint4*)&As[ra][ca + 8] = pa1;
        *(uint4*)&Bs[rb][cb]     = pb;
        __syncthreads();
        if (c0 + 32 < Cn) {
            pa0 = *(const uint4*)(A + (size_t)(c0 + 32 + ra) * Sn + s0 + ca);
            pa1 = *(const uint4*)(A + (size_t)(c0 + 32 + ra) * Sn + s0 + ca + 8);
            pb  = *(const uint4*)(Wt + (size_t)(o0 + rb) * Cn + c0 + 32 + cb);
        }
#pragma unroll
        for (int kk = 0; kk < 32; kk += 16) {
            unsigned af[2][4];
#pragma unroll
            for (int im = 0; im < 2; im++) {
                unsigned addr = (unsigned)__cvta_generic_to_shared(
                    &As[kk + a_kr][wm + im * 16 + a_mc]);
                asm volatile(
                    "ldmatrix.sync.aligned.m8n8.x4.trans.shared.b16 {%0,%1,%2,%3},[%4];\n"
                    : "=r"(af[im][0]), "=r"(af[im][1]), "=r"(af[im][2]), "=r"(af[im][3])
                    : "r"(addr));
            }
#pragma unroll
            for (int jn = 0; jn < 4; jn++) {
                unsigned b0 = *(const unsigned*)&Bs[wn + jn * 8 + g][kk + 2 * t];
                unsigned b1 = *(const unsigned*)&Bs[wn + jn * 8 + g][kk + 2 * t + 8];
#pragma unroll
                for (int im = 0; im < 2; im++) mma_bf16(acc[im][jn], af[im], b0, b1);
            }
        }
        __syncthreads();
    }

    __nv_bfloat16* ob = out + (size_t)b * Sn * Cn;
#pragma unroll
    for (int im = 0; im < 2; im++) {
        int m = s0 + wm + im * 16 + g;
#pragma unroll
        for (int jn = 0; jn < 4; jn++) {
            int n = o0 + wn + jn * 8 + 2 * t;
            float b0f = bias[n], b1f = bias[n + 1];
            __nv_bfloat162 v0 = __floats2bfloat162_rn(acc[im][jn][0] + b0f, acc[im][jn][1] + b1f);
            __nv_bfloat162 v1 = __floats2bfloat162_rn(acc[im][jn][2] + b0f, acc[im][jn][3] + b1f);
            *(unsigned*)(ob + (size_t)m * Cn + n)       = *(unsigned*)&v0;
            *(unsigned*)(ob + (size_t)(m + 8) * Cn + n) = *(unsigned*)&v1;
        }
    }
}

// ---------------------------------------------------------------------------
// Scores + diag softmax. Block = (jg, ig, b): M=128 rows m=ii*32+h (q rows
// h*32 + ig*4+ii), N=128 cols n=jj*32+H (k rows H*32 + jg*4+jj), K=512.
// Each 32x32 softmax group (ii,jj) lives entirely in one warp -> shuffle-only
// reductions. Writes g_D[b][i*32+j].
// ---------------------------------------------------------------------------
__global__ void __launch_bounds__(256) scores_kernel() {
    int b = blockIdx.z, ig = blockIdx.y, jg = blockIdx.x;
    const __nv_bfloat16* Qb = g_Qt + (size_t)b * Sn * Cn;
    const __nv_bfloat16* Kb = g_Kt + (size_t)b * Sn * Cn;

    __shared__ __align__(16) __nv_bfloat16 Qs[128][40];  // [m][k]
    __shared__ __align__(16) __nv_bfloat16 Ks[128][40];  // [n][k]

    int tid = threadIdx.x, lane = tid & 31, warp = tid >> 5;
    int wm = (warp & 3) * 32, wn = (warp >> 2) * 64;
    int g = lane >> 2, t = lane & 3;

    int rr = tid >> 1, koff = (tid & 1) * 16;
    int s1 = (rr & 31) * 32 + ig * 4 + (rr >> 5);
    int s2 = (rr & 31) * 32 + jg * 4 + (rr >> 5);
    const __nv_bfloat16* qrow = Qb + (size_t)s1 * Cn;
    const __nv_bfloat16* krow = Kb + (size_t)s2 * Cn;

    uint4 pq0 = *(const uint4*)(qrow + koff);
    uint4 pq1 = *(const uint4*)(qrow + koff + 8);
    uint4 pk0 = *(const uint4*)(krow + koff);
    uint4 pk1 = *(const uint4*)(krow + koff + 8);

    float acc[2][8][4] = {};
    for (int c0 = 0; c0 < Cn; c0 += 32) {
        *(uint4*)&Qs[rr][koff]     = pq0;
        *(uint4*)&Qs[rr][koff + 8] = pq1;
        *(uint4*)&Ks[rr][koff]     = pk0;
        *(uint4*)&Ks[rr][koff + 8] = pk1;
        __syncthreads();
        if (c0 + 32 < Cn) {
            pq0 = *(const uint4*)(qrow + c0 + 32 + koff);
            pq1 = *(const uint4*)(qrow + c0 + 32 + koff + 8);
            pk0 = *(const uint4*)(krow + c0 + 32 + koff);
            pk1 = *(const uint4*)(krow + c0 + 32 + koff + 8);
        }
#pragma unroll
        for (int kk = 0; kk < 32; kk += 16) {
            unsigned af[2][4];
#pragma unroll
            for (int im = 0; im < 2; im++) {
                int r = wm + im * 16 + g;
                af[im][0] = *(const unsigned*)&Qs[r][kk + 2 * t];
                af[im][1] = *(const unsigned*)&Qs[r + 8][kk + 2 * t];
                af[im][2] = *(const unsigned*)&Qs[r][kk + 2 * t + 8];
                af[im][3] = *(const unsigned*)&Qs[r + 8][kk + 2 * t + 8];
            }
#pragma unroll
            for (int jn = 0; jn < 8; jn++) {
                unsigned b0 = *(const unsigned*)&Ks[wn + jn * 8 + g][kk + 2 * t];
                unsigned b1 = *(const unsigned*)&Ks[wn + jn * 8 + g][kk + 2 * t + 8];
#pragma unroll
                for (int im = 0; im < 2; im++) mma_bf16(acc[im][jn], af[im], b0, b1);
            }
        }
        __syncthreads();
    }

    const float scale = 0.04419417382415922f;  // 512^-0.5
#pragma unroll
    for (int im = 0; im < 2; im++)
#pragma unroll
        for (int jn = 0; jn < 8; jn++)
#pragma unroll
            for (int r = 0; r < 4; r++) acc[im][jn][r] *= scale;

    int ii = warp & 3;
#pragma unroll
    for (int side = 0; side < 2; side++) {
        int jj = (wn >> 5) + side;
        float mx = -1e30f;
#pragma unroll
        for (int im = 0; im < 2; im++)
#pragma unroll
            for (int j4 = 0; j4 < 4; j4++)
#pragma unroll
                for (int r = 0; r < 4; r++) mx = fmaxf(mx, acc[im][side * 4 + j4][r]);
#pragma unroll
        for (int off = 16; off; off >>= 1) mx = fmaxf(mx, __shfl_xor_sync(0xffffffffu, mx, off));

        float se = 0.f;
#pragma unroll
        for (int im = 0; im < 2; im++)
#pragma unroll
            for (int j4 = 0; j4 < 4; j4++)
#pragma unroll
                for (int r = 0; r < 4; r++) se += __expf(acc[im][side * 4 + j4][r] - mx);
#pragma unroll
        for (int off = 16; off; off >>= 1) se += __shfl_xor_sync(0xffffffffu, se, off);

        int i = ig * 4 + ii, j = jg * 4 + jj;
        int rl = ig * 4 + ii;                // local row of diag within warp tile
        int cl = side * 32 + jg * 4 + jj;    // local col of diag within warp tile
        int im_d = rl >> 4, rlow = rl & 15, half = rlow >> 3, gg = rlow & 7;
        int jn_d = cl >> 3, tt = (cl & 7) >> 1, par = cl & 1;
        int reg = half * 2 + par;
        float cand = 0.f;
#pragma unroll
        for (int im = 0; im < 2; im++)
#pragma unroll
            for (int jn = 0; jn < 8; jn++)
#pragma unroll
                for (int r = 0; r < 4; r++)
                    if (im == im_d && jn == jn_d && r == reg) cand = acc[im][jn][r];
        float dv = __shfl_sync(0xffffffffu, cand, gg * 4 + tt);
        if (lane == 0) g_D[b * Sn + i * 32 + j] = __expf(dv - mx) / se;
    }
}

// ---------------------------------------------------------------------------
// Final GEMM: out[b][c][s] = x + D[b][s] * (sum_o Wn[o][c]*Vt[b][s][o]) + bn[c]
// A = Wnt[c][o] ([m][k], direct LDS), B = Vt[s][o] ([n][k], direct LDS).
// Block 128(m=c) x 64(n=s).
// ---------------------------------------------------------------------------
__global__ void __launch_bounds__(256) final_kernel(const float* __restrict__ x,
                                                    const float* __restrict__ bn,
                                                    float* __restrict__ out) {
    int b = blockIdx.z, m0 = blockIdx.x * 128, n0 = blockIdx.y * 64;
    const __nv_bfloat16* Bsrc = g_Vt + (size_t)b * Sn * Cn;

    __shared__ __align__(16) __nv_bfloat16 As[128][40];  // [m][k]
    __shared__ __align__(16) __nv_bfloat16 Bs[64][40];   // [n][k]
    __shared__ float Ds[64];

    int tid = threadIdx.x, lane = tid & 31, warp = tid >> 5;
    int wm = (warp & 3) * 32, wn = (warp >> 2) * 32;
    int g = lane >> 2, t = lane & 3;

    int ra = tid >> 1, ca = (tid & 1) * 16;
    int rb = tid >> 2, cb = (tid & 3) * 8;

    if (tid < 64) Ds[tid] = g_D[b * Sn + n0 + tid];

    uint4 pa0 = *(const uint4*)(g_Wnt + (size_t)(m0 + ra) * Cn + ca);
    uint4 pa1 = *(const uint4*)(g_Wnt + (size_t)(m0 + ra) * Cn + ca + 8);
    uint4 pb  = *(const uint4*)(Bsrc + (size_t)(n0 + rb) * Cn + cb);

    float acc[2][4][4] = {};
    for (int c0 = 0; c0 < Cn; c0 += 32) {
        *(uint4*)&As[ra][ca]     = pa0;
        *(uint4*)&As[ra][ca + 8] = pa1;
        *(uint4*)&Bs[rb][cb]     = pb;
        __syncthreads();
        if (c0 + 32 < Cn) {
            pa0 = *(const uint4*)(g_Wnt + (size_t)(m0 + ra) * Cn + c0 + 32 + ca);
            pa1 = *(const uint4*)(g_Wnt + (size_t)(m0 + ra) * Cn + c0 + 32 + ca + 8);
            pb  = *(const uint4*)(Bsrc + (size_t)(n0 + rb) * Cn + c0 + 32 + cb);
        }
#pragma unroll
        for (int kk = 0; kk < 32; kk += 16) {
            unsigned af[2][4];
#pragma unroll
            for (int im = 0; im < 2; im++) {
                int r = wm + im * 16 + g;
                af[im][0] = *(const unsigned*)&As[r][kk + 2 * t];
                af[im][1] = *(const unsigned*)&As[r + 8][kk + 2 * t];
                af[im][2] = *(const unsigned*)&As[r][kk + 2 * t + 8];
                af[im][3] = *(const unsigned*)&As[r + 8][kk + 2 * t + 8];
            }
#pragma unroll
            for (int jn = 0; jn < 4; jn++) {
                unsigned b0 = *(const unsigned*)&Bs[wn + jn * 8 + g][kk + 2 * t];
                unsigned b1 = *(const unsigned*)&Bs[wn + jn * 8 + g][kk + 2 * t + 8];
#pragma unroll
                for (int im = 0; im < 2; im++) mma_bf16(acc[im][jn], af[im], b0, b1);
            }
        }
        __syncthreads();
    }

#pragma unroll
    for (int im = 0; im < 2; im++) {
        int m = m0 + wm + im * 16 + g;
        float bb0 = bn[m], bb1 = bn[m + 8];
#pragma unroll
        for (int jn = 0; jn < 4; jn++) {
            int n = n0 + wn + jn * 8 + 2 * t;
            float d0 = Ds[n - n0], d1 = Ds[n - n0 + 1];
            size_t idx = ((size_t)b * Cn + m) * Sn + n;
            float2 xr = *(const float2*)(x + idx);
            float2 o0v = {xr.x + d0 * acc[im][jn][0] + bb0,
                          xr.y + d1 * acc[im][jn][1] + bb0};
            *(float2*)(out + idx) = o0v;
            size_t idx2 = idx + 8 * (size_t)Sn;
            float2 xr2 = *(const float2*)(x + idx2);
            float2 o1v = {xr2.x + d0 * acc[im][jn][2] + bb1,
                          xr2.y + d1 * acc[im][jn][3] + bb1};
            *(float2*)(out + idx2) = o1v;
        }
    }
}

// ---------------------------------------------------------------------------
extern "C" void kernel_launch(void* const* d_in, const int* in_sizes, int n_in,
                              void* d_out, int out_size) {
    const float* x  = (const float*)d_in[0];
    const float* Wq = (const float*)d_in[1];
    const float* bq = (const float*)d_in[2];
    const float* Wk = (const float*)d_in[3];
    const float* bk = (const float*)d_in[4];
    const float* Wv = (const float*)d_in[5];
    const float* bv = (const float*)d_in[6];
    const float* Wn = (const float*)d_in[7];
    const float* bn = (const float*)d_in[8];
    float* out = (float*)d_out;

    __nv_bfloat16 *pQt, *pKt, *pVt, *pWqt, *pWkt, *pWvt;
    cudaGetSymbolAddress((void**)&pQt,  g_Qt);
    cudaGetSymbolAddress((void**)&pKt,  g_Kt);
    cudaGetSymbolAddress((void**)&pVt,  g_Vt);
    cudaGetSymbolAddress((void**)&pWqt, g_Wqt);
    cudaGetSymbolAddress((void**)&pWkt, g_Wkt);
    cudaGetSymbolAddress((void**)&pWvt, g_Wvt);

    wconv_kernel<<<dim3(16, 16, 4), 256>>>(Wq, Wk, Wv, Wn);
    gn_kernel<<<Bn * 32, 256>>>(x);

    dim3 gP(Sn / 128, Cn / 64, Bn);  // (8, 8, 16)
    proj_kernel<<<gP, 256>>>(pWqt, bq, pQt);
    proj_kernel<<<gP, 256>>>(pWkt, bk, pKt);
    proj_kernel<<<gP, 256>>>(pWvt, bv, pVt);

    scores_kernel<<<dim3(8, 8, Bn), 256>>>();

    final_kernel<<<dim3(Cn / 128, Sn / 64, Bn), 256>>>(x, bn, out);
}

// round 6
// speedup vs baseline: 5.6733x; 1.2743x over previous
#include <cuda_runtime.h>
#include <cuda_bf16.h>

#define Bn 16
#define Cn 512
#define Sn 1024

// ---- scratch (no allocs allowed) ----
__device__ __nv_bfloat16 g_hn [Bn * Cn * Sn];   // [b][c][s]  (k-major for proj A)
__device__ __nv_bfloat16 g_Qt [Bn * Sn * Cn];   // [b][s][o]
__device__ __nv_bfloat16 g_Kt [Bn * Sn * Cn];   // [b][s][o]
__device__ __nv_bfloat16 g_Vt [Bn * Sn * Cn];   // [b][s][o]
__device__ __nv_bfloat16 g_Wqt[Cn * Cn];        // W^T : [out][in] bf16
__device__ __nv_bfloat16 g_Wkt[Cn * Cn];
__device__ __nv_bfloat16 g_Wvt[Cn * Cn];
__device__ __nv_bfloat16 g_Wnt[Cn * Cn];
__device__ float         g_D  [Bn * Sn];        // diag softmax

// ---------------------------------------------------------------------------
__device__ __forceinline__ void mma_bf16(float c[4], const unsigned a[4],
                                         unsigned b0, unsigned b1) {
    asm volatile(
        "mma.sync.aligned.m16n8k16.row.col.f32.bf16.bf16.f32 "
        "{%0,%1,%2,%3},{%4,%5,%6,%7},{%8,%9},{%0,%1,%2,%3};\n"
        : "+f"(c[0]), "+f"(c[1]), "+f"(c[2]), "+f"(c[3])
        : "r"(a[0]), "r"(a[1]), "r"(a[2]), "r"(a[3]), "r"(b0), "r"(b1));
}

__device__ __forceinline__ void cp16(void* dst, const void* src) {
    unsigned d = (unsigned)__cvta_generic_to_shared(dst);
    asm volatile("cp.async.cg.shared.global [%0], [%1], 16;\n" :: "r"(d), "l"(src));
}
__device__ __forceinline__ void cp_commit() {
    asm volatile("cp.async.commit_group;\n");
}
template <int N> __device__ __forceinline__ void cp_wait() {
    asm volatile("cp.async.wait_group %0;\n" :: "n"(N));
}

// ---------------------------------------------------------------------------
// Weight transpose+convert: Wt[out][in] bf16 = W[in][out] fp32.
// ---------------------------------------------------------------------------
__global__ void __launch_bounds__(256) wconv_kernel(const float* __restrict__ Wq,
                                                    const float* __restrict__ Wk,
                                                    const float* __restrict__ Wv,
                                                    const float* __restrict__ Wn) {
    __shared__ float t[32][33];
    int w = blockIdx.z;
    const float* src = (w == 0) ? Wq : (w == 1) ? Wk : (w == 2) ? Wv : Wn;
    __nv_bfloat16* dst = (w == 0) ? g_Wqt : (w == 1) ? g_Wkt : (w == 2) ? g_Wvt : g_Wnt;
    int c0 = blockIdx.x * 32, r0 = blockIdx.y * 32;
    int tx = threadIdx.x & 31, ty = threadIdx.x >> 5;
#pragma unroll
    for (int i = 0; i < 4; i++)
        t[ty + i * 8][tx] = src[(size_t)(r0 + ty + i * 8) * Cn + c0 + tx];
    __syncthreads();
#pragma unroll
    for (int i = 0; i < 4; i++)
        dst[(size_t)(c0 + ty + i * 8) * Cn + r0 + tx] = __float2bfloat16(t[tx][ty + i * 8]);
}

// ---------------------------------------------------------------------------
// GroupNorm: one block per (b, group). Whole group tile kept in registers.
// ---------------------------------------------------------------------------
__global__ void __launch_bounds__(256) gn_kernel(const float* __restrict__ x) {
    int b = blockIdx.x >> 5, g = blockIdx.x & 31;
    size_t base = ((size_t)b * Cn + g * 16) * Sn;
    const float4* x4 = (const float4*)(x + base);
    int tid = threadIdx.x;

    float4 v[16];
    float s = 0.f, ss = 0.f;
#pragma unroll
    for (int i = 0; i < 16; i++) {
        v[i] = x4[tid + i * 256];
        s  += v[i].x + v[i].y + v[i].z + v[i].w;
        ss += v[i].x * v[i].x + v[i].y * v[i].y + v[i].z * v[i].z + v[i].w * v[i].w;
    }
    __shared__ float rs[256], rq[256];
    rs[tid] = s; rq[tid] = ss;
    __syncthreads();
    for (int off = 128; off; off >>= 1) {
        if (tid < off) { rs[tid] += rs[tid + off]; rq[tid] += rq[tid + off]; }
        __syncthreads();
    }
    const float invN = 1.f / 16384.f;
    float mean = rs[0] * invN;
    float var  = rq[0] * invN - mean * mean;
    float inv  = rsqrtf(var + 1e-5f);

    uint2* h2 = (uint2*)(g_hn + base);
#pragma unroll
    for (int i = 0; i < 16; i++) {
        __nv_bfloat162 p0 = __floats2bfloat162_rn((v[i].x - mean) * inv, (v[i].y - mean) * inv);
        __nv_bfloat162 p1 = __floats2bfloat162_rn((v[i].z - mean) * inv, (v[i].w - mean) * inv);
        uint2 u; u.x = *(unsigned*)&p0; u.y = *(unsigned*)&p1;
        h2[tid + i * 256] = u;
    }
}

// ---------------------------------------------------------------------------
// Fused Q/K/V projection GEMM, cp.async double-buffered.
// blockIdx.z = w*16 + b  (w in {0,1,2} selects weight/bias/output).
// out[b][s][o] = sum_c hn[b][c][s] * W[c][o] + bias[o]
// Block 128(m=s) x 64(n=o), BK=32, 8 warps (4x2), warp tile 32x32.
// ---------------------------------------------------------------------------
__global__ void __launch_bounds__(256) proj_kernel(const float* __restrict__ bq,
                                                   const float* __restrict__ bk,
                                                   const float* __restrict__ bv) {
    int z = blockIdx.z, w = z >> 4, b = z & 15;
    const __nv_bfloat16* Wt = (w == 0) ? g_Wqt : (w == 1) ? g_Wkt : g_Wvt;
    const float* bias = (w == 0) ? bq : (w == 1) ? bk : bv;
    __nv_bfloat16* out = ((w == 0) ? g_Qt : (w == 1) ? g_Kt : g_Vt) + (size_t)b * Sn * Cn;

    int s0 = blockIdx.x * 128, o0 = blockIdx.y * 64;
    const __nv_bfloat16* A = g_hn + (size_t)b * Cn * Sn;

    __shared__ __align__(16) __nv_bfloat16 As[2][32][136];  // [k][m]
    __shared__ __align__(16) __nv_bfloat16 Bs[2][64][40];   // [n][k]

    int tid = threadIdx.x, lane = tid & 31, warp = tid >> 5;
    int wm = (warp & 3) * 32, wn = (warp >> 2) * 32;
    int g = lane >> 2, t = lane & 3;

    int ra = tid >> 3, ca = (tid & 7) * 16;  // As loader: 32 rows x 128 cols
    int rb = tid >> 2, cb = (tid & 3) * 8;   // Bs loader: 64 rows x 32 cols

    int mi = lane >> 3;
    int a_kr = (lane & 7) + ((mi >> 1) << 3);
    int a_mc = (mi & 1) << 3;

    auto issue = [&](int c0, int st) {
        cp16(&As[st][ra][ca],     A + (size_t)(c0 + ra) * Sn + s0 + ca);
        cp16(&As[st][ra][ca + 8], A + (size_t)(c0 + ra) * Sn + s0 + ca + 8);
        cp16(&Bs[st][rb][cb],     Wt + (size_t)(o0 + rb) * Cn + c0 + cb);
        cp_commit();
    };
    issue(0, 0);
    issue(32, 1);

    float acc[2][4][4] = {};
#pragma unroll 1
    for (int it = 0; it < 16; it++) {
        if (it < 14) cp_wait<1>(); else cp_wait<0>();
        __syncthreads();
        int st = it & 1;
#pragma unroll
        for (int kk = 0; kk < 32; kk += 16) {
            unsigned af[2][4];
#pragma unroll
            for (int im = 0; im < 2; im++) {
                unsigned addr = (unsigned)__cvta_generic_to_shared(
                    &As[st][kk + a_kr][wm + im * 16 + a_mc]);
                asm volatile(
                    "ldmatrix.sync.aligned.m8n8.x4.trans.shared.b16 {%0,%1,%2,%3},[%4];\n"
                    : "=r"(af[im][0]), "=r"(af[im][1]), "=r"(af[im][2]), "=r"(af[im][3])
                    : "r"(addr));
            }
#pragma unroll
            for (int jn = 0; jn < 4; jn++) {
                unsigned b0 = *(const unsigned*)&Bs[st][wn + jn * 8 + g][kk + 2 * t];
                unsigned b1 = *(const unsigned*)&Bs[st][wn + jn * 8 + g][kk + 2 * t + 8];
#pragma unroll
                for (int im = 0; im < 2; im++) mma_bf16(acc[im][jn], af[im], b0, b1);
            }
        }
        __syncthreads();
        if (it + 2 < 16) issue((it + 2) * 32, st);
    }

#pragma unroll
    for (int im = 0; im < 2; im++) {
        int m = s0 + wm + im * 16 + g;
#pragma unroll
        for (int jn = 0; jn < 4; jn++) {
            int n = o0 + wn + jn * 8 + 2 * t;
            float b0f = bias[n], b1f = bias[n + 1];
            __nv_bfloat162 v0 = __floats2bfloat162_rn(acc[im][jn][0] + b0f, acc[im][jn][1] + b1f);
            __nv_bfloat162 v1 = __floats2bfloat162_rn(acc[im][jn][2] + b0f, acc[im][jn][3] + b1f);
            *(unsigned*)(out + (size_t)m * Cn + n)       = *(unsigned*)&v0;
            *(unsigned*)(out + (size_t)(m + 8) * Cn + n) = *(unsigned*)&v1;
        }
    }
}

// ---------------------------------------------------------------------------
// Scores + diag softmax, cp.async double-buffered.
// Block = (jg, ig, b): 128x128 score tile, K=512; each 32x32 softmax group
// lives in one warp -> shuffle-only reductions. Writes g_D[b][i*32+j].
// ---------------------------------------------------------------------------
__global__ void __launch_bounds__(256) scores_kernel() {
    int b = blockIdx.z, ig = blockIdx.y, jg = blockIdx.x;
    const __nv_bfloat16* Qb = g_Qt + (size_t)b * Sn * Cn;
    const __nv_bfloat16* Kb = g_Kt + (size_t)b * Sn * Cn;

    __shared__ __align__(16) __nv_bfloat16 Qs[2][128][40];  // [m][k]
    __shared__ __align__(16) __nv_bfloat16 Ks[2][128][40];  // [n][k]

    int tid = threadIdx.x, lane = tid & 31, warp = tid >> 5;
    int wm = (warp & 3) * 32, wn = (warp >> 2) * 64;
    int g = lane >> 2, t = lane & 3;

    int rr = tid >> 1, koff = (tid & 1) * 16;
    int s1 = (rr & 31) * 32 + ig * 4 + (rr >> 5);
    int s2 = (rr & 31) * 32 + jg * 4 + (rr >> 5);
    const __nv_bfloat16* qrow = Qb + (size_t)s1 * Cn;
    const __nv_bfloat16* krow = Kb + (size_t)s2 * Cn;

    auto issue = [&](int c0, int st) {
        cp16(&Qs[st][rr][koff],     qrow + c0 + koff);
        cp16(&Qs[st][rr][koff + 8], qrow + c0 + koff + 8);
        cp16(&Ks[st][rr][koff],     krow + c0 + koff);
        cp16(&Ks[st][rr][koff + 8], krow + c0 + koff + 8);
        cp_commit();
    };
    issue(0, 0);
    issue(32, 1);

    float acc[2][8][4] = {};
#pragma unroll 1
    for (int it = 0; it < 16; it++) {
        if (it < 14) cp_wait<1>(); else cp_wait<0>();
        __syncthreads();
        int st = it & 1;
#pragma unroll
        for (int kk = 0; kk < 32; kk += 16) {
            unsigned af[2][4];
#pragma unroll
            for (int im = 0; im < 2; im++) {
                int r = wm + im * 16 + g;
                af[im][0] = *(const unsigned*)&Qs[st][r][kk + 2 * t];
                af[im][1] = *(const unsigned*)&Qs[st][r + 8][kk + 2 * t];
                af[im][2] = *(const unsigned*)&Qs[st][r][kk + 2 * t + 8];
                af[im][3] = *(const unsigned*)&Qs[st][r + 8][kk + 2 * t + 8];
            }
#pragma unroll
            for (int jn = 0; jn < 8; jn++) {
                unsigned b0 = *(const unsigned*)&Ks[st][wn + jn * 8 + g][kk + 2 * t];
                unsigned b1 = *(const unsigned*)&Ks[st][wn + jn * 8 + g][kk + 2 * t + 8];
#pragma unroll
                for (int im = 0; im < 2; im++) mma_bf16(acc[im][jn], af[im], b0, b1);
            }
        }
        __syncthreads();
        if (it + 2 < 16) issue((it + 2) * 32, st);
    }

    const float scale = 0.04419417382415922f;  // 512^-0.5
#pragma unroll
    for (int im = 0; im < 2; im++)
#pragma unroll
        for (int jn = 0; jn < 8; jn++)
#pragma unroll
            for (int r = 0; r < 4; r++) acc[im][jn][r] *= scale;

    int ii = warp & 3;
#pragma unroll
    for (int side = 0; side < 2; side++) {
        int jj = (wn >> 5) + side;
        float mx = -1e30f;
#pragma unroll
        for (int im = 0; im < 2; im++)
#pragma unroll
            for (int j4 = 0; j4 < 4; j4++)
#pragma unroll
                for (int r = 0; r < 4; r++) mx = fmaxf(mx, acc[im][side * 4 + j4][r]);
#pragma unroll
        for (int off = 16; off; off >>= 1) mx = fmaxf(mx, __shfl_xor_sync(0xffffffffu, mx, off));

        float se = 0.f;
#pragma unroll
        for (int im = 0; im < 2; im++)
#pragma unroll
            for (int j4 = 0; j4 < 4; j4++)
#pragma unroll
                for (int r = 0; r < 4; r++) se += __expf(acc[im][side * 4 + j4][r] - mx);
#pragma unroll
        for (int off = 16; off; off >>= 1) se += __shfl_xor_sync(0xffffffffu, se, off);

        int i = ig * 4 + ii, j = jg * 4 + jj;
        int rl = ig * 4 + ii;                // local row of diag within warp tile
        int cl = side * 32 + jg * 4 + jj;    // local col of diag within warp tile
        int im_d = rl >> 4, rlow = rl & 15, half = rlow >> 3, gg = rlow & 7;
        int jn_d = cl >> 3, tt = (cl & 7) >> 1, par = cl & 1;
        int reg = half * 2 + par;
        float cand = 0.f;
#pragma unroll
        for (int im = 0; im < 2; im++)
#pragma unroll
            for (int jn = 0; jn < 8; jn++)
#pragma unroll
                for (int r = 0; r < 4; r++)
                    if (im == im_d && jn == jn_d && r == reg) cand = acc[im][jn][r];
        float dv = __shfl_sync(0xffffffffu, cand, gg * 4 + tt);
        if (lane == 0) g_D[b * Sn + i * 32 + j] = __expf(dv - mx) / se;
    }
}

// ---------------------------------------------------------------------------
// Final GEMM, cp.async double-buffered:
// out[b][c][s] = x + D[b][s] * (sum_o Wn[o][c]*Vt[b][s][o]) + bn[c]
// Block 128(m=c) x 64(n=s).
// ---------------------------------------------------------------------------
__global__ void __launch_bounds__(256) final_kernel(const float* __restrict__ x,
                                                    const float* __restrict__ bn,
                                                    float* __restrict__ out) {
    int b = blockIdx.z, m0 = blockIdx.x * 128, n0 = blockIdx.y * 64;
    const __nv_bfloat16* Bsrc = g_Vt + (size_t)b * Sn * Cn;

    __shared__ __align__(16) __nv_bfloat16 As[2][128][40];  // [m][k]
    __shared__ __align__(16) __nv_bfloat16 Bs[2][64][40];   // [n][k]
    __shared__ float Ds[64];

    int tid = threadIdx.x, lane = tid & 31, warp = tid >> 5;
    int wm = (warp & 3) * 32, wn = (warp >> 2) * 32;
    int g = lane >> 2, t = lane & 3;

    int ra = tid >> 1, ca = (tid & 1) * 16;
    int rb = tid >> 2, cb = (tid & 3) * 8;

    if (tid < 64) Ds[tid] = g_D[b * Sn + n0 + tid];

    auto issue = [&](int c0, int st) {
        cp16(&As[st][ra][ca],     g_Wnt + (size_t)(m0 + ra) * Cn + c0 + ca);
        cp16(&As[st][ra][ca + 8], g_Wnt + (size_t)(m0 + ra) * Cn + c0 + ca + 8);
        cp16(&Bs[st][rb][cb],     Bsrc + (size_t)(n0 + rb) * Cn + c0 + cb);
        cp_commit();
    };
    issue(0, 0);
    issue(32, 1);

    float acc[2][4][4] = {};
#pragma unroll 1
    for (int it = 0; it < 16; it++) {
        if (it < 14) cp_wait<1>(); else cp_wait<0>();
        __syncthreads();
        int st = it & 1;
#pragma unroll
        for (int kk = 0; kk < 32; kk += 16) {
            unsigned af[2][4];
#pragma unroll
            for (int im = 0; im < 2; im++) {
                int r = wm + im * 16 + g;
                af[im][0] = *(const unsigned*)&As[st][r][kk + 2 * t];
                af[im][1] = *(const unsigned*)&As[st][r + 8][kk + 2 * t];
                af[im][2] = *(const unsigned*)&As[st][r][kk + 2 * t + 8];
                af[im][3] = *(const unsigned*)&As[st][r + 8][kk + 2 * t + 8];
            }
#pragma unroll
            for (int jn = 0; jn < 4; jn++) {
                unsigned b0 = *(const unsigned*)&Bs[st][wn + jn * 8 + g][kk + 2 * t];
                unsigned b1 = *(const unsigned*)&Bs[st][wn + jn * 8 + g][kk + 2 * t + 8];
#pragma unroll
                for (int im = 0; im < 2; im++) mma_bf16(acc[im][jn], af[im], b0, b1);
            }
        }
        __syncthreads();
        if (it + 2 < 16) issue((it + 2) * 32, st);
    }

#pragma unroll
    for (int im = 0; im < 2; im++) {
        int m = m0 + wm + im * 16 + g;
        float bb0 = bn[m], bb1 = bn[m + 8];
#pragma unroll
        for (int jn = 0; jn < 4; jn++) {
            int n = n0 + wn + jn * 8 + 2 * t;
            float d0 = Ds[n - n0], d1 = Ds[n - n0 + 1];
            size_t idx = ((size_t)b * Cn + m) * Sn + n;
            float2 xr = *(const float2*)(x + idx);
            float2 o0v = {xr.x + d0 * acc[im][jn][0] + bb0,
                          xr.y + d1 * acc[im][jn][1] + bb0};
            *(float2*)(out + idx) = o0v;
            size_t idx2 = idx + 8 * (size_t)Sn;
            float2 xr2 = *(const float2*)(x + idx2);
            float2 o1v = {xr2.x + d0 * acc[im][jn][2] + bb1,
                          xr2.y + d1 * acc[im][jn][3] + bb1};
            *(float2*)(out + idx2) = o1v;
        }
    }
}

// ---------------------------------------------------------------------------
extern "C" void kernel_launch(void* const* d_in, const int* in_sizes, int n_in,
                              void* d_out, int out_size) {
    const float* x  = (const float*)d_in[0];
    const float* Wq = (const float*)d_in[1];
    const float* bq = (const float*)d_in[2];
    const float* Wk = (const float*)d_in[3];
    const float* bk = (const float*)d_in[4];
    const float* Wv = (const float*)d_in[5];
    const float* bv = (const float*)d_in[6];
    const float* Wn = (const float*)d_in[7];
    const float* bn = (const float*)d_in[8];
    float* out = (float*)d_out;

    wconv_kernel<<<dim3(16, 16, 4), 256>>>(Wq, Wk, Wv, Wn);
    gn_kernel<<<Bn * 32, 256>>>(x);

    proj_kernel<<<dim3(8, 8, 48), 256>>>(bq, bk, bv);

    scores_kernel<<<dim3(8, 8, Bn), 256>>>();

    final_kernel<<<dim3(Cn / 128, Sn / 64, Bn), 256>>>(x, bn, out);
}

// round 7
// speedup vs baseline: 5.8647x; 1.0338x over previous
#include <cuda_runtime.h>
#include <cuda_fp16.h>

#define Bn 16
#define Cn 512
#define Sn 1024

// ---- scratch (no allocs allowed) ----
__device__ __half g_hn [Bn * Cn * Sn];   // [b][c][s]  (k-major for proj A)
__device__ __half g_Qt [Bn * Sn * Cn];   // [b][s][o]  (scale folded in)
__device__ __half g_Kt [Bn * Sn * Cn];   // [b][s][o]
__device__ __half g_Vt [Bn * Sn * Cn];   // [b][s][o]
__device__ __half g_Wqt[Cn * Cn];        // W^T : [out][in]
__device__ __half g_Wkt[Cn * Cn];
__device__ __half g_Wvt[Cn * Cn];
__device__ __half g_Wnt[Cn * Cn];
__device__ float  g_D  [Bn * Sn];        // diag softmax

// ---------------------------------------------------------------------------
__device__ __forceinline__ void mma_f16(unsigned c[2], const unsigned a[4],
                                        unsigned b0, unsigned b1) {
    asm volatile(
        "mma.sync.aligned.m16n8k16.row.col.f16.f16.f16.f16 "
        "{%0,%1},{%2,%3,%4,%5},{%6,%7},{%0,%1};\n"
        : "+r"(c[0]), "+r"(c[1])
        : "r"(a[0]), "r"(a[1]), "r"(a[2]), "r"(a[3]), "r"(b0), "r"(b1));
}

__device__ __forceinline__ void cp16(void* dst, const void* src) {
    unsigned d = (unsigned)__cvta_generic_to_shared(dst);
    asm volatile("cp.async.cg.shared.global [%0], [%1], 16;\n" :: "r"(d), "l"(src));
}
__device__ __forceinline__ void cp_commit() {
    asm volatile("cp.async.commit_group;\n");
}
template <int N> __device__ __forceinline__ void cp_wait() {
    asm volatile("cp.async.wait_group %0;\n" :: "n"(N));
}

// ---------------------------------------------------------------------------
// Weight transpose+convert: Wt[out][in] f16 = W[in][out] fp32.
// ---------------------------------------------------------------------------
__global__ void __launch_bounds__(256) wconv_kernel(const float* __restrict__ Wq,
                                                    const float* __restrict__ Wk,
                                                    const float* __restrict__ Wv,
                                                    const float* __restrict__ Wn) {
    __shared__ float t[32][33];
    int w = blockIdx.z;
    const float* src = (w == 0) ? Wq : (w == 1) ? Wk : (w == 2) ? Wv : Wn;
    __half* dst = (w == 0) ? g_Wqt : (w == 1) ? g_Wkt : (w == 2) ? g_Wvt : g_Wnt;
    int c0 = blockIdx.x * 32, r0 = blockIdx.y * 32;
    int tx = threadIdx.x & 31, ty = threadIdx.x >> 5;
#pragma unroll
    for (int i = 0; i < 4; i++)
        t[ty + i * 8][tx] = src[(size_t)(r0 + ty + i * 8) * Cn + c0 + tx];
    __syncthreads();
#pragma unroll
    for (int i = 0; i < 4; i++)
        dst[(size_t)(c0 + ty + i * 8) * Cn + r0 + tx] = __float2half(t[tx][ty + i * 8]);
}

// ---------------------------------------------------------------------------
// GroupNorm: one block per (b, group); whole group tile in registers. -> f16
// ---------------------------------------------------------------------------
__global__ void __launch_bounds__(256) gn_kernel(const float* __restrict__ x) {
    int b = blockIdx.x >> 5, g = blockIdx.x & 31;
    size_t base = ((size_t)b * Cn + g * 16) * Sn;
    const float4* x4 = (const float4*)(x + base);
    int tid = threadIdx.x;

    float4 v[16];
    float s = 0.f, ss = 0.f;
#pragma unroll
    for (int i = 0; i < 16; i++) {
        v[i] = x4[tid + i * 256];
        s  += v[i].x + v[i].y + v[i].z + v[i].w;
        ss += v[i].x * v[i].x + v[i].y * v[i].y + v[i].z * v[i].z + v[i].w * v[i].w;
    }
    __shared__ float rs[256], rq[256];
    rs[tid] = s; rq[tid] = ss;
    __syncthreads();
    for (int off = 128; off; off >>= 1) {
        if (tid < off) { rs[tid] += rs[tid + off]; rq[tid] += rq[tid + off]; }
        __syncthreads();
    }
    const float invN = 1.f / 16384.f;
    float mean = rs[0] * invN;
    float var  = rq[0] * invN - mean * mean;
    float inv  = rsqrtf(var + 1e-5f);

    uint2* h2 = (uint2*)(g_hn + base);
#pragma unroll
    for (int i = 0; i < 16; i++) {
        __half2 p0 = __floats2half2_rn((v[i].x - mean) * inv, (v[i].y - mean) * inv);
        __half2 p1 = __floats2half2_rn((v[i].z - mean) * inv, (v[i].w - mean) * inv);
        uint2 u; u.x = *(unsigned*)&p0; u.y = *(unsigned*)&p1;
        h2[tid + i * 256] = u;
    }
}

// ---------------------------------------------------------------------------
// Fused Q/K/V projection GEMM, cp.async double-buffered, f16 acc.
// blockIdx.z = w*16 + b.  out[b][s][o] = (sum_c hn[c][s]*W[c][o] + bias[o])*qs
// Block 128(m=s) x 64(n=o), BK=32, 8 warps (4x2), warp tile 32x32.
// ---------------------------------------------------------------------------
__global__ void __launch_bounds__(256) proj_kernel(const float* __restrict__ bq,
                                                   const float* __restrict__ bk,
                                                   const float* __restrict__ bv) {
    int z = blockIdx.z, w = z >> 4, b = z & 15;
    const __half* Wt = (w == 0) ? g_Wqt : (w == 1) ? g_Wkt : g_Wvt;
    const float* bias = (w == 0) ? bq : (w == 1) ? bk : bv;
    __half* out = ((w == 0) ? g_Qt : (w == 1) ? g_Kt : g_Vt) + (size_t)b * Sn * Cn;
    const float qs = (w == 0) ? 0.04419417382415922f : 1.f;  // 512^-0.5 into Q

    int s0 = blockIdx.x * 128, o0 = blockIdx.y * 64;
    const __half* A = g_hn + (size_t)b * Cn * Sn;

    __shared__ __align__(16) __half As[2][32][136];  // [k][m]
    __shared__ __align__(16) __half Bs[2][64][40];   // [n][k]

    int tid = threadIdx.x, lane = tid & 31, warp = tid >> 5;
    int wm = (warp & 3) * 32, wn = (warp >> 2) * 32;
    int g = lane >> 2, t = lane & 3;

    int ra = tid >> 3, ca = (tid & 7) * 16;  // As loader: 32 rows x 128 cols
    int rb = tid >> 2, cb = (tid & 3) * 8;   // Bs loader: 64 rows x 32 cols

    int mi = lane >> 3;
    int a_kr = (lane & 7) + ((mi >> 1) << 3);
    int a_mc = (mi & 1) << 3;

    auto issue = [&](int c0, int st) {
        cp16(&As[st][ra][ca],     A + (size_t)(c0 + ra) * Sn + s0 + ca);
        cp16(&As[st][ra][ca + 8], A + (size_t)(c0 + ra) * Sn + s0 + ca + 8);
        cp16(&Bs[st][rb][cb],     Wt + (size_t)(o0 + rb) * Cn + c0 + cb);
        cp_commit();
    };
    issue(0, 0);
    issue(32, 1);

    unsigned acc[2][4][2] = {};
#pragma unroll 1
    for (int it = 0; it < 16; it++) {
        if (it < 14) cp_wait<1>(); else cp_wait<0>();
        __syncthreads();
        int st = it & 1;
#pragma unroll
        for (int kk = 0; kk < 32; kk += 16) {
            unsigned af[2][4];
#pragma unroll
            for (int im = 0; im < 2; im++) {
                unsigned addr = (unsigned)__cvta_generic_to_shared(
                    &As[st][kk + a_kr][wm + im * 16 + a_mc]);
                asm volatile(
                    "ldmatrix.sync.aligned.m8n8.x4.trans.shared.b16 {%0,%1,%2,%3},[%4];\n"
                    : "=r"(af[im][0]), "=r"(af[im][1]), "=r"(af[im][2]), "=r"(af[im][3])
                    : "r"(addr));
            }
#pragma unroll
            for (int jn = 0; jn < 4; jn++) {
                unsigned b0 = *(const unsigned*)&Bs[st][wn + jn * 8 + g][kk + 2 * t];
                unsigned b1 = *(const unsigned*)&Bs[st][wn + jn * 8 + g][kk + 2 * t + 8];
#pragma unroll
                for (int im = 0; im < 2; im++) mma_f16(acc[im][jn], af[im], b0, b1);
            }
        }
        __syncthreads();
        if (it + 2 < 16) issue((it + 2) * 32, st);
    }

#pragma unroll
    for (int im = 0; im < 2; im++) {
        int m = s0 + wm + im * 16 + g;
#pragma unroll
        for (int jn = 0; jn < 4; jn++) {
            int n = o0 + wn + jn * 8 + 2 * t;
            float b0f = bias[n], b1f = bias[n + 1];
            float2 lo = __half22float2(*(__half2*)&acc[im][jn][0]);
            float2 hi = __half22float2(*(__half2*)&acc[im][jn][1]);
            __half2 v0 = __floats2half2_rn((lo.x + b0f) * qs, (lo.y + b1f) * qs);
            __half2 v1 = __floats2half2_rn((hi.x + b0f) * qs, (hi.y + b1f) * qs);
            *(unsigned*)(out + (size_t)m * Cn + n)       = *(unsigned*)&v0;
            *(unsigned*)(out + (size_t)(m + 8) * Cn + n) = *(unsigned*)&v1;
        }
    }
}

// ---------------------------------------------------------------------------
// Scores + diag softmax; 512 threads, 4x4 warps, warp tile 32x32, f16 acc.
// Block (jg, ig, b): rows m=ii*32+h (q rows h*32+ig*4+ii), cols n=jj*32+H
// (k rows H*32+jg*4+jj), K=512. Each warp owns one 32x32 softmax group.
// ---------------------------------------------------------------------------
__global__ void __launch_bounds__(512) scores_kernel() {
    int b = blockIdx.z, ig = blockIdx.y, jg = blockIdx.x;
    const __half* Qb = g_Qt + (size_t)b * Sn * Cn;
    const __half* Kb = g_Kt + (size_t)b * Sn * Cn;

    __shared__ __align__(16) __half Qs[2][128][40];  // [m][k]
    __shared__ __align__(16) __half Ks[2][128][40];  // [n][k]

    int tid = threadIdx.x, lane = tid & 31, warp = tid >> 5;
    int ii = warp & 3, jj = warp >> 2;
    int wm = ii * 32, wn = jj * 32;
    int g = lane >> 2, t = lane & 3;

    int rr = tid >> 2, koff = (tid & 3) * 8;
    int s1 = (rr & 31) * 32 + ig * 4 + (rr >> 5);
    int s2 = (rr & 31) * 32 + jg * 4 + (rr >> 5);
    const __half* qrow = Qb + (size_t)s1 * Cn;
    const __half* krow = Kb + (size_t)s2 * Cn;

    auto issue = [&](int c0, int st) {
        cp16(&Qs[st][rr][koff], qrow + c0 + koff);
        cp16(&Ks[st][rr][koff], krow + c0 + koff);
        cp_commit();
    };
    issue(0, 0);
    issue(32, 1);

    unsigned acc[2][4][2] = {};
#pragma unroll 1
    for (int it = 0; it < 16; it++) {
        if (it < 14) cp_wait<1>(); else cp_wait<0>();
        __syncthreads();
        int st = it & 1;
#pragma unroll
        for (int kk = 0; kk < 32; kk += 16) {
            unsigned af[2][4];
#pragma unroll
            for (int im = 0; im < 2; im++) {
                int r = wm + im * 16 + g;
                af[im][0] = *(const unsigned*)&Qs[st][r][kk + 2 * t];
                af[im][1] = *(const unsigned*)&Qs[st][r + 8][kk + 2 * t];
                af[im][2] = *(const unsigned*)&Qs[st][r][kk + 2 * t + 8];
                af[im][3] = *(const unsigned*)&Qs[st][r + 8][kk + 2 * t + 8];
            }
#pragma unroll
            for (int jn = 0; jn < 4; jn++) {
                unsigned b0 = *(const unsigned*)&Ks[st][wn + jn * 8 + g][kk + 2 * t];
                unsigned b1 = *(const unsigned*)&Ks[st][wn + jn * 8 + g][kk + 2 * t + 8];
#pragma unroll
                for (int im = 0; im < 2; im++) mma_f16(acc[im][jn], af[im], b0, b1);
            }
        }
        __syncthreads();
        if (it + 2 < 16) issue((it + 2) * 32, st);
    }

    // per-warp softmax over its 32x32 group (scale already folded into Q)
    float mx = -1e30f;
#pragma unroll
    for (int im = 0; im < 2; im++)
#pragma unroll
        for (int jn = 0; jn < 4; jn++)
#pragma unroll
            for (int r = 0; r < 2; r++) {
                float2 f = __half22float2(*(__half2*)&acc[im][jn][r]);
                mx = fmaxf(mx, fmaxf(f.x, f.y));
            }
#pragma unroll
    for (int off = 16; off; off >>= 1) mx = fmaxf(mx, __shfl_xor_sync(0xffffffffu, mx, off));

    float se = 0.f;
#pragma unroll
    for (int im = 0; im < 2; im++)
#pragma unroll
        for (int jn = 0; jn < 4; jn++)
#pragma unroll
            for (int r = 0; r < 2; r++) {
                float2 f = __half22float2(*(__half2*)&acc[im][jn][r]);
                se += __expf(f.x - mx) + __expf(f.y - mx);
            }
#pragma unroll
    for (int off = 16; off; off >>= 1) se += __shfl_xor_sync(0xffffffffu, se, off);

    // diag element at local (row = ig*4+ii, col = jg*4+jj)
    int rl = ig * 4 + ii, cl = jg * 4 + jj;
    int im_d = rl >> 4, rlow = rl & 15, reg_d = rlow >> 3, g_d = rlow & 7;
    int jn_d = cl >> 3, t_d = (cl & 7) >> 1, par = cl & 1;
    float cand = 0.f;
#pragma unroll
    for (int im = 0; im < 2; im++)
#pragma unroll
        for (int jn = 0; jn < 4; jn++)
#pragma unroll
            for (int r = 0; r < 2; r++)
                if (im == im_d && jn == jn_d && r == reg_d) {
                    float2 f = __half22float2(*(__half2*)&acc[im][jn][r]);
                    cand = par ? f.y : f.x;
                }
    float dv = __shfl_sync(0xffffffffu, cand, g_d * 4 + t_d);
    if (lane == 0) {
        int i = ig * 4 + ii, j = jg * 4 + jj;
        g_D[b * Sn + i * 32 + j] = __expf(dv - mx) / se;
    }
}

// ---------------------------------------------------------------------------
// Final GEMM, f16 acc: out[b][c][s] = x + D[b][s]*(sum_o Wn[o][c]*Vt[b][s][o]) + bn[c]
// Block 128(m=c) x 64(n=s).
// ---------------------------------------------------------------------------
__global__ void __launch_bounds__(256) final_kernel(const float* __restrict__ x,
                                                    const float* __restrict__ bn,
                                                    float* __restrict__ out) {
    int b = blockIdx.z, m0 = blockIdx.x * 128, n0 = blockIdx.y * 64;
    const __half* Bsrc = g_Vt + (size_t)b * Sn * Cn;

    __shared__ __align__(16) __half As[2][128][40];  // [m][k]
    __shared__ __align__(16) __half Bs[2][64][40];   // [n][k]
    __shared__ float Ds[64];

    int tid = threadIdx.x, lane = tid & 31, warp = tid >> 5;
    int wm = (warp & 3) * 32, wn = (warp >> 2) * 32;
    int g = lane >> 2, t = lane & 3;

    int ra = tid >> 1, ca = (tid & 1) * 16;
    int rb = tid >> 2, cb = (tid & 3) * 8;

    if (tid < 64) Ds[tid] = g_D[b * Sn + n0 + tid];

    auto issue = [&](int c0, int st) {
        cp16(&As[st][ra][ca],     g_Wnt + (size_t)(m0 + ra) * Cn + c0 + ca);
        cp16(&As[st][ra][ca + 8], g_Wnt + (size_t)(m0 + ra) * Cn + c0 + ca + 8);
        cp16(&Bs[st][rb][cb],     Bsrc + (size_t)(n0 + rb) * Cn + c0 + cb);
        cp_commit();
    };
    issue(0, 0);
    issue(32, 1);

    unsigned acc[2][4][2] = {};
#pragma unroll 1
    for (int it = 0; it < 16; it++) {
        if (it < 14) cp_wait<1>(); else cp_wait<0>();
        __syncthreads();
        int st = it & 1;
#pragma unroll
        for (int kk = 0; kk < 32; kk += 16) {
            unsigned af[2][4];
#pragma unroll
            for (int im = 0; im < 2; im++) {
                int r = wm + im * 16 + g;
                af[im][0] = *(const unsigned*)&As[st][r][kk + 2 * t];
                af[im][1] = *(const unsigned*)&As[st][r + 8][kk + 2 * t];
                af[im][2] = *(const unsigned*)&As[st][r][kk + 2 * t + 8];
                af[im][3] = *(const unsigned*)&As[st][r + 8][kk + 2 * t + 8];
            }
#pragma unroll
            for (int jn = 0; jn < 4; jn++) {
                unsigned b0 = *(const unsigned*)&Bs[st][wn + jn * 8 + g][kk + 2 * t];
                unsigned b1 = *(const unsigned*)&Bs[st][wn + jn * 8 + g][kk + 2 * t + 8];
#pragma unroll
                for (int im = 0; im < 2; im++) mma_f16(acc[im][jn], af[im], b0, b1);
            }
        }
        __syncthreads();
        if (it + 2 < 16) issue((it + 2) * 32, st);
    }

#pragma unroll
    for (int im = 0; im < 2; im++) {
        int m = m0 + wm + im * 16 + g;
        float bb0 = bn[m], bb1 = bn[m + 8];
#pragma unroll
        for (int jn = 0; jn < 4; jn++) {
            int n = n0 + wn + jn * 8 + 2 * t;
            float d0 = Ds[n - n0], d1 = Ds[n - n0 + 1];
            float2 lo = __half22float2(*(__half2*)&acc[im][jn][0]);
            float2 hi = __half22float2(*(__half2*)&acc[im][jn][1]);
            size_t idx = ((size_t)b * Cn + m) * Sn + n;
            float2 xr = *(const float2*)(x + idx);
            float2 o0v = {xr.x + d0 * lo.x + bb0, xr.y + d1 * lo.y + bb0};
            *(float2*)(out + idx) = o0v;
            size_t idx2 = idx + 8 * (size_t)Sn;
            float2 xr2 = *(const float2*)(x + idx2);
            float2 o1v = {xr2.x + d0 * hi.x + bb1, xr2.y + d1 * hi.y + bb1};
            *(float2*)(out + idx2) = o1v;
        }
    }
}

// ---------------------------------------------------------------------------
extern "C" void kernel_launch(void* const* d_in, const int* in_sizes, int n_in,
                              void* d_out, int out_size) {
    const float* x  = (const float*)d_in[0];
    const float* Wq = (const float*)d_in[1];
    const float* bq = (const float*)d_in[2];
    const float* Wk = (const float*)d_in[3];
    const float* bk = (const float*)d_in[4];
    const float* Wv = (const float*)d_in[5];
    const float* bv = (const float*)d_in[6];
    const float* Wn = (const float*)d_in[7];
    const float* bn = (const float*)d_in[8];
    float* out = (float*)d_out;

    wconv_kernel<<<dim3(16, 16, 4), 256>>>(Wq, Wk, Wv, Wn);
    gn_kernel<<<Bn * 32, 256>>>(x);

    proj_kernel<<<dim3(8, 8, 48), 256>>>(bq, bk, bv);

    scores_kernel<<<dim3(8, 8, Bn), 512>>>();

    final_kernel<<<dim3(Cn / 128, Sn / 64, Bn), 256>>>(x, bn, out);
}

// round 9
// speedup vs baseline: 6.2513x; 1.0659x over previous
#include <cuda_runtime.h>
#include <cuda_fp16.h>

#define Bn 16
#define Cn 512
#define Sn 1024

// ---- scratch (no allocs allowed) ----
__device__ __half g_hn [Bn * Cn * Sn];   // [b][c][s]  (k-major for proj A)
__device__ __half g_Qt [Bn * Sn * Cn];   // [b][s][o]  (scale folded in)
__device__ __half g_Kt [Bn * Sn * Cn];   // [b][s][o]
__device__ __half g_Vt [Bn * Sn * Cn];   // [b][s][o]
__device__ __half g_Wqt[Cn * Cn];        // W^T : [out][in]
__device__ __half g_Wkt[Cn * Cn];
__device__ __half g_Wvt[Cn * Cn];
__device__ __half g_Wnt[Cn * Cn];
__device__ float  g_D  [Bn * Sn];        // diag softmax

// ---------------------------------------------------------------------------
__device__ __forceinline__ void mma_f16(unsigned c[2], const unsigned a[4],
                                        unsigned b0, unsigned b1) {
    asm volatile(
        "mma.sync.aligned.m16n8k16.row.col.f16.f16.f16.f16 "
        "{%0,%1},{%2,%3,%4,%5},{%6,%7},{%0,%1};\n"
        : "+r"(c[0]), "+r"(c[1])
        : "r"(a[0]), "r"(a[1]), "r"(a[2]), "r"(a[3]), "r"(b0), "r"(b1));
}

__device__ __forceinline__ void ldm_x4(unsigned f[4], const void* p) {
    unsigned addr = (unsigned)__cvta_generic_to_shared(p);
    asm volatile(
        "ldmatrix.sync.aligned.m8n8.x4.shared.b16 {%0,%1,%2,%3},[%4];\n"
        : "=r"(f[0]), "=r"(f[1]), "=r"(f[2]), "=r"(f[3]) : "r"(addr));
}

__device__ __forceinline__ void cp16(void* dst, const void* src) {
    unsigned d = (unsigned)__cvta_generic_to_shared(dst);
    asm volatile("cp.async.cg.shared.global [%0], [%1], 16;\n" :: "r"(d), "l"(src));
}
__device__ __forceinline__ void cp_commit() {
    asm volatile("cp.async.commit_group;\n");
}
template <int N> __device__ __forceinline__ void cp_wait() {
    asm volatile("cp.async.wait_group %0;\n" :: "n"(N));
}

// ---------------------------------------------------------------------------
// Weight transpose+convert: Wt[out][in] f16 = W[in][out] fp32.
// ---------------------------------------------------------------------------
__global__ void __launch_bounds__(256) wconv_kernel(const float* __restrict__ Wq,
                                                    const float* __restrict__ Wk,
                                                    const float* __restrict__ Wv,
                                                    const float* __restrict__ Wn) {
    __shared__ float t[32][33];
    int w = blockIdx.z;
    const float* src = (w == 0) ? Wq : (w == 1) ? Wk : (w == 2) ? Wv : Wn;
    __half* dst = (w == 0) ? g_Wqt : (w == 1) ? g_Wkt : (w == 2) ? g_Wvt : g_Wnt;
    int c0 = blockIdx.x * 32, r0 = blockIdx.y * 32;
    int tx = threadIdx.x & 31, ty = threadIdx.x >> 5;
#pragma unroll
    for (int i = 0; i < 4; i++)
        t[ty + i * 8][tx] = src[(size_t)(r0 + ty + i * 8) * Cn + c0 + tx];
    __syncthreads();
#pragma unroll
    for (int i = 0; i < 4; i++)
        dst[(size_t)(c0 + ty + i * 8) * Cn + r0 + tx] = __float2half(t[tx][ty + i * 8]);
}

// ---------------------------------------------------------------------------
// GroupNorm: one block per (b, group); whole group tile in registers. -> f16
// ---------------------------------------------------------------------------
__global__ void __launch_bounds__(256) gn_kernel(const float* __restrict__ x) {
    int b = blockIdx.x >> 5, g = blockIdx.x & 31;
    size_t base = ((size_t)b * Cn + g * 16) * Sn;
    const float4* x4 = (const float4*)(x + base);
    int tid = threadIdx.x;

    float4 v[16];
    float s = 0.f, ss = 0.f;
#pragma unroll
    for (int i = 0; i < 16; i++) {
        v[i] = x4[tid + i * 256];
        s  += v[i].x + v[i].y + v[i].z + v[i].w;
        ss += v[i].x * v[i].x + v[i].y * v[i].y + v[i].z * v[i].z + v[i].w * v[i].w;
    }
    __shared__ float rs[256], rq[256];
    rs[tid] = s; rq[tid] = ss;
    __syncthreads();
    for (int off = 128; off; off >>= 1) {
        if (tid < off) { rs[tid] += rs[tid + off]; rq[tid] += rq[tid + off]; }
        __syncthreads();
    }
    const float invN = 1.f / 16384.f;
    float mean = rs[0] * invN;
    float var  = rq[0] * invN - mean * mean;
    float inv  = rsqrtf(var + 1e-5f);

    uint2* h2 = (uint2*)(g_hn + base);
#pragma unroll
    for (int i = 0; i < 16; i++) {
        __half2 p0 = __floats2half2_rn((v[i].x - mean) * inv, (v[i].y - mean) * inv);
        __half2 p1 = __floats2half2_rn((v[i].z - mean) * inv, (v[i].w - mean) * inv);
        uint2 u; u.x = *(unsigned*)&p0; u.y = *(unsigned*)&p1;
        h2[tid + i * 256] = u;
    }
}

// ---------------------------------------------------------------------------
// Fused Q/K/V projection GEMM, cp.async double-buffered, f16 acc.
// blockIdx.z = w*16 + b.  out[b][s][o] = (sum_c hn[c][s]*W[c][o] + bias[o])*qs
// Block 128(m=s) x 64(n=o), BK=32, 8 warps (4x2), warp tile 32x32.
// A frags via ldmatrix.trans (k-major), B frags via ldmatrix.x4.
// ---------------------------------------------------------------------------
__global__ void __launch_bounds__(256) proj_kernel(const float* __restrict__ bq,
                                                   const float* __restrict__ bk,
                                                   const float* __restrict__ bv) {
    int z = blockIdx.z, w = z >> 4, b = z & 15;
    const __half* Wt = (w == 0) ? g_Wqt : (w == 1) ? g_Wkt : g_Wvt;
    const float* bias = (w == 0) ? bq : (w == 1) ? bk : bv;
    __half* out = ((w == 0) ? g_Qt : (w == 1) ? g_Kt : g_Vt) + (size_t)b * Sn * Cn;
    const float qs = (w == 0) ? 0.04419417382415922f : 1.f;  // 512^-0.5 into Q

    int s0 = blockIdx.x * 128, o0 = blockIdx.y * 64;
    const __half* A = g_hn + (size_t)b * Cn * Sn;

    __shared__ __align__(16) __half As[2][32][136];  // [k][m]
    __shared__ __align__(16) __half Bs[2][64][40];   // [n][k]

    int tid = threadIdx.x, lane = tid & 31, warp = tid >> 5;
    int wm = (warp & 3) * 32, wn = (warp >> 2) * 32;

    int ra = tid >> 3, ca = (tid & 7) * 16;  // As loader: 32 rows x 128 cols
    int rb = tid >> 2, cb = (tid & 3) * 8;   // Bs loader: 64 rows x 32 cols

    int mi = lane >> 3;
    int a_kr = (lane & 7) + ((mi >> 1) << 3);
    int a_mc = (mi & 1) << 3;

    // ldmatrix.x4 lane addressing for B ([n][k]):
    int q4 = lane >> 3, r8 = lane & 7;
    int b_ro = ((q4 >> 1) << 3) + r8, b_co = (q4 & 1) << 3;

    auto issue = [&](int c0, int st) {
        cp16(&As[st][ra][ca],     A + (size_t)(c0 + ra) * Sn + s0 + ca);
        cp16(&As[st][ra][ca + 8], A + (size_t)(c0 + ra) * Sn + s0 + ca + 8);
        cp16(&Bs[st][rb][cb],     Wt + (size_t)(o0 + rb) * Cn + c0 + cb);
        cp_commit();
    };
    issue(0, 0);
    issue(32, 1);

    unsigned acc[2][4][2] = {};
#pragma unroll 1
    for (int it = 0; it < 16; it++) {
        if (it < 14) cp_wait<1>(); else cp_wait<0>();
        __syncthreads();
        int st = it & 1;
#pragma unroll
        for (int kk = 0; kk < 32; kk += 16) {
            unsigned af[2][4], bf[2][4];
#pragma unroll
            for (int im = 0; im < 2; im++) {
                unsigned addr = (unsigned)__cvta_generic_to_shared(
                    &As[st][kk + a_kr][wm + im * 16 + a_mc]);
                asm volatile(
                    "ldmatrix.sync.aligned.m8n8.x4.trans.shared.b16 {%0,%1,%2,%3},[%4];\n"
                    : "=r"(af[im][0]), "=r"(af[im][1]), "=r"(af[im][2]), "=r"(af[im][3])
                    : "r"(addr));
            }
#pragma unroll
            for (int jp = 0; jp < 2; jp++)
                ldm_x4(bf[jp], &Bs[st][wn + jp * 16 + b_ro][kk + b_co]);
#pragma unroll
            for (int jp = 0; jp < 2; jp++)
#pragma unroll
                for (int im = 0; im < 2; im++) {
                    mma_f16(acc[im][2 * jp],     af[im], bf[jp][0], bf[jp][1]);
                    mma_f16(acc[im][2 * jp + 1], af[im], bf[jp][2], bf[jp][3]);
                }
        }
        __syncthreads();
        if (it + 2 < 16) issue((it + 2) * 32, st);
    }

    int g = lane >> 2, t = lane & 3;
#pragma unroll
    for (int im = 0; im < 2; im++) {
        int m = s0 + wm + im * 16 + g;
#pragma unroll
        for (int jn = 0; jn < 4; jn++) {
            int n = o0 + wn + jn * 8 + 2 * t;
            float b0f = bias[n], b1f = bias[n + 1];
            float2 lo = __half22float2(*(__half2*)&acc[im][jn][0]);
            float2 hi = __half22float2(*(__half2*)&acc[im][jn][1]);
            __half2 v0 = __floats2half2_rn((lo.x + b0f) * qs, (lo.y + b1f) * qs);
            __half2 v1 = __floats2half2_rn((hi.x + b0f) * qs, (hi.y + b1f) * qs);
            *(unsigned*)(out + (size_t)m * Cn + n)       = *(unsigned*)&v0;
            *(unsigned*)(out + (size_t)(m + 8) * Cn + n) = *(unsigned*)&v1;
        }
    }
}

// ---------------------------------------------------------------------------
// Scores + diag softmax; 512 threads, 4x4 warps, warp tile 32x32, f16 acc.
// All fragments via ldmatrix.x4 (non-trans) from [row][k] stride-40 smem.
// Block (jg, ig, b): rows m=ii*32+h (q rows h*32+ig*4+ii), cols n=jj*32+H
// (k rows H*32+jg*4+jj), K=512. Each warp owns one 32x32 softmax group.
// ---------------------------------------------------------------------------
__global__ void __launch_bounds__(512) scores_kernel() {
    int b = blockIdx.z, ig = blockIdx.y, jg = blockIdx.x;
    const __half* Qb = g_Qt + (size_t)b * Sn * Cn;
    const __half* Kb = g_Kt + (size_t)b * Sn * Cn;

    __shared__ __align__(16) __half Qs[2][128][40];  // [m][k]
    __shared__ __align__(16) __half Ks[2][128][40];  // [n][k]

    int tid = threadIdx.x, lane = tid & 31, warp = tid >> 5;
    int ii = warp & 3, jj = warp >> 2;
    int wm = ii * 32, wn = jj * 32;

    int rr = tid >> 2, koff = (tid & 3) * 8;
    int s1 = (rr & 31) * 32 + ig * 4 + (rr >> 5);
    int s2 = (rr & 31) * 32 + jg * 4 + (rr >> 5);
    const __half* qrow = Qb + (size_t)s1 * Cn;
    const __half* krow = Kb + (size_t)s2 * Cn;

    // ldmatrix.x4 lane addressing
    int q4 = lane >> 3, r8 = lane & 7;
    int a_ro = ((q4 & 1) << 3) + r8, a_co = (q4 >> 1) << 3;   // A: m-rows, k-cols
    int b_ro = ((q4 >> 1) << 3) + r8, b_co = (q4 & 1) << 3;   // B: n-rows, k-cols

    auto issue = [&](int c0, int st) {
        cp16(&Qs[st][rr][koff], qrow + c0 + koff);
        cp16(&Ks[st][rr][koff], krow + c0 + koff);
        cp_commit();
    };
    issue(0, 0);
    issue(32, 1);

    unsigned acc[2][4][2] = {};
#pragma unroll 1
    for (int it = 0; it < 16; it++) {
        if (it < 14) cp_wait<1>(); else cp_wait<0>();
        __syncthreads();
        int st = it & 1;
#pragma unroll
        for (int kk = 0; kk < 32; kk += 16) {
            unsigned af[2][4], bf[2][4];
#pragma unroll
            for (int im = 0; im < 2; im++)
                ldm_x4(af[im], &Qs[st][wm + im * 16 + a_ro][kk + a_co]);
#pragma unroll
            for (int jp = 0; jp < 2; jp++)
                ldm_x4(bf[jp], &Ks[st][wn + jp * 16 + b_ro][kk + b_co]);
#pragma unroll
            for (int jp = 0; jp < 2; jp++)
#pragma unroll
                for (int im = 0; im < 2; im++) {
                    mma_f16(acc[im][2 * jp],     af[im], bf[jp][0], bf[jp][1]);
                    mma_f16(acc[im][2 * jp + 1], af[im], bf[jp][2], bf[jp][3]);
                }
        }
        __syncthreads();
        if (it + 2 < 16) issue((it + 2) * 32, st);
    }

    // per-warp softmax over its 32x32 group (scale already folded into Q)
    float mx = -1e30f;
#pragma unroll
    for (int im = 0; im < 2; im++)
#pragma unroll
        for (int jn = 0; jn < 4; jn++)
#pragma unroll
            for (int r = 0; r < 2; r++) {
                float2 f = __half22float2(*(__half2*)&acc[im][jn][r]);
                mx = fmaxf(mx, fmaxf(f.x, f.y));
            }
#pragma unroll
    for (int off = 16; off; off >>= 1) mx = fmaxf(mx, __shfl_xor_sync(0xffffffffu, mx, off));

    float se = 0.f;
#pragma unroll
    for (int im = 0; im < 2; im++)
#pragma unroll
        for (int jn = 0; jn < 4; jn++)
#pragma unroll
            for (int r = 0; r < 2; r++) {
                float2 f = __half22float2(*(__half2*)&acc[im][jn][r]);
                se += __expf(f.x - mx) + __expf(f.y - mx);
            }
#pragma unroll
    for (int off = 16; off; off >>= 1) se += __shfl_xor_sync(0xffffffffu, se, off);

    // diag element at local (row = ig*4+ii, col = jg*4+jj)
    int rl = ig * 4 + ii, cl = jg * 4 + jj;
    int im_d = rl >> 4, rlow = rl & 15, reg_d = rlow >> 3, g_d = rlow & 7;
    int jn_d = cl >> 3, t_d = (cl & 7) >> 1, par = cl & 1;
    float cand = 0.f;
#pragma unroll
    for (int im = 0; im < 2; im++)
#pragma unroll
        for (int jn = 0; jn < 4; jn++)
#pragma unroll
            for (int r = 0; r < 2; r++)
                if (im == im_d && jn == jn_d && r == reg_d) {
                    float2 f = __half22float2(*(__half2*)&acc[im][jn][r]);
                    cand = par ? f.y : f.x;
                }
    float dv = __shfl_sync(0xffffffffu, cand, g_d * 4 + t_d);
    if (lane == 0) {
        int i = ig * 4 + ii, j = jg * 4 + jj;
        g_D[b * Sn + i * 32 + j] = __expf(dv - mx) / se;
    }
}

// ---------------------------------------------------------------------------
// Final GEMM, f16 acc: out[b][c][s] = x + D[b][s]*(sum_o Wn[o][c]*Vt[b][s][o]) + bn[c]
// Block 128(m=c) x 64(n=s). All fragments via ldmatrix.x4.
// ---------------------------------------------------------------------------
__global__ void __launch_bounds__(256) final_kernel(const float* __restrict__ x,
                                                    const float* __restrict__ bn,
                                                    float* __restrict__ out) {
    int b = blockIdx.z, m0 = blockIdx.x * 128, n0 = blockIdx.y * 64;
    const __half* Bsrc = g_Vt + (size_t)b * Sn * Cn;

    __shared__ __align__(16) __half As[2][128][40];  // [m][k]
    __shared__ __align__(16) __half Bs[2][64][40];   // [n][k]
    __shared__ float Ds[64];

    int tid = threadIdx.x, lane = tid & 31, warp = tid >> 5;
    int wm = (warp & 3) * 32, wn = (warp >> 2) * 32;

    int ra = tid >> 1, ca = (tid & 1) * 16;
    int rb = tid >> 2, cb = (tid & 3) * 8;

    int q4 = lane >> 3, r8 = lane & 7;
    int a_ro = ((q4 & 1) << 3) + r8, a_co = (q4 >> 1) << 3;
    int b_ro = ((q4 >> 1) << 3) + r8, b_co = (q4 & 1) << 3;

    if (tid < 64) Ds[tid] = g_D[b * Sn + n0 + tid];

    auto issue = [&](int c0, int st) {
        cp16(&As[st][ra][ca],     g_Wnt + (size_t)(m0 + ra) * Cn + c0 + ca);
        cp16(&As[st][ra][ca + 8], g_Wnt + (size_t)(m0 + ra) * Cn + c0 + ca + 8);
        cp16(&Bs[st][rb][cb],     Bsrc + (size_t)(n0 + rb) * Cn + c0 + cb);
        cp_commit();
    };
    issue(0, 0);
    issue(32, 1);

    unsigned acc[2][4][2] = {};
#pragma unroll 1
    for (int it = 0; it < 16; it++) {
        if (it < 14) cp_wait<1>(); else cp_wait<0>();
        __syncthreads();
        int st = it & 1;
#pragma unroll
        for (int kk = 0; kk < 32; kk += 16) {
            unsigned af[2][4], bf[2][4];
#pragma unroll
            for (int im = 0; im < 2; im++)
                ldm_x4(af[im], &As[st][wm + im * 16 + a_ro][kk + a_co]);
#pragma unroll
            for (int jp = 0; jp < 2; jp++)
                ldm_x4(bf[jp], &Bs[st][wn + jp * 16 + b_ro][kk + b_co]);
#pragma unroll
            for (int jp = 0; jp < 2; jp++)
#pragma unroll
                for (int im = 0; im < 2; im++) {
                    mma_f16(acc[im][2 * jp],     af[im], bf[jp][0], bf[jp][1]);
                    mma_f16(acc[im][2 * jp + 1], af[im], bf[jp][2], bf[jp][3]);
                }
        }
        __syncthreads();
        if (it + 2 < 16) issue((it + 2) * 32, st);
    }

    int g = lane >> 2, t = lane & 3;
#pragma unroll
    for (int im = 0; im < 2; im++) {
        int m = m0 + wm + im * 16 + g;
        float bb0 = bn[m], bb1 = bn[m + 8];
#pragma unroll
        for (int jn = 0; jn < 4; jn++) {
            int n = n0 + wn + jn * 8 + 2 * t;
            float d0 = Ds[n - n0], d1 = Ds[n - n0 + 1];
            float2 lo = __half22float2(*(__half2*)&acc[im][jn][0]);
            float2 hi = __half22float2(*(__half2*)&acc[im][jn][1]);
            size_t idx = ((size_t)b * Cn + m) * Sn + n;
            float2 xr = *(const float2*)(x + idx);
            float2 o0v = {xr.x + d0 * lo.x + bb0, xr.y + d1 * lo.y + bb0};
            *(float2*)(out + idx) = o0v;
            size_t idx2 = idx + 8 * (size_t)Sn;
            float2 xr2 = *(const float2*)(x + idx2);
            float2 o1v = {xr2.x + d0 * hi.x + bb1, xr2.y + d1 * hi.y + bb1};
            *(float2*)(out + idx2) = o1v;
        }
    }
}

// ---------------------------------------------------------------------------
extern "C" void kernel_launch(void* const* d_in, const int* in_sizes, int n_in,
                              void* d_out, int out_size) {
    const float* x  = (const float*)d_in[0];
    const float* Wq = (const float*)d_in[1];
    const float* bq = (const float*)d_in[2];
    const float* Wk = (const float*)d_in[3];
    const float* bk = (const float*)d_in[4];
    const float* Wv = (const float*)d_in[5];
    const float* bv = (const float*)d_in[6];
    const float* Wn = (const float*)d_in[7];
    const float* bn = (const float*)d_in[8];
    float* out = (float*)d_out;

    wconv_kernel<<<dim3(16, 16, 4), 256>>>(Wq, Wk, Wv, Wn);
    gn_kernel<<<Bn * 32, 256>>>(x);

    proj_kernel<<<dim3(8, 8, 48), 256>>>(bq, bk, bv);

    scores_kernel<<<dim3(8, 8, Bn), 512>>>();

    final_kernel<<<dim3(Cn / 128, Sn / 64, Bn), 256>>>(x, bn, out);
}

// round 10
// speedup vs baseline: 6.4751x; 1.0358x over previous
#include <cuda_runtime.h>
#include <cuda_fp16.h>

#define Bn 16
#define Cn 512
#define Sn 1024

// ---- scratch (no allocs allowed) ----
__device__ __half g_hn [Bn * Cn * Sn];   // [b][c][s]  (k-major for proj A)
__device__ __half g_Qt [Bn * Sn * Cn];   // [b][s][o]  (scale folded in)
__device__ __half g_Kt [Bn * Sn * Cn];   // [b][s][o]
__device__ __half g_Vt [Bn * Sn * Cn];   // [b][s][o]
__device__ __half g_Wqt[Cn * Cn];        // W^T : [out][in]
__device__ __half g_Wkt[Cn * Cn];
__device__ __half g_Wvt[Cn * Cn];
__device__ __half g_Wnt[Cn * Cn];
__device__ float  g_D  [Bn * Sn];        // diag softmax

// ---------------------------------------------------------------------------
__device__ __forceinline__ void mma_f16(unsigned c[2], const unsigned a[4],
                                        unsigned b0, unsigned b1) {
    asm volatile(
        "mma.sync.aligned.m16n8k16.row.col.f16.f16.f16.f16 "
        "{%0,%1},{%2,%3,%4,%5},{%6,%7},{%0,%1};\n"
        : "+r"(c[0]), "+r"(c[1])
        : "r"(a[0]), "r"(a[1]), "r"(a[2]), "r"(a[3]), "r"(b0), "r"(b1));
}

__device__ __forceinline__ void ldm_x4(unsigned f[4], const void* p) {
    unsigned addr = (unsigned)__cvta_generic_to_shared(p);
    asm volatile(
        "ldmatrix.sync.aligned.m8n8.x4.shared.b16 {%0,%1,%2,%3},[%4];\n"
        : "=r"(f[0]), "=r"(f[1]), "=r"(f[2]), "=r"(f[3]) : "r"(addr));
}

__device__ __forceinline__ void cp16(void* dst, const void* src) {
    unsigned d = (unsigned)__cvta_generic_to_shared(dst);
    asm volatile("cp.async.cg.shared.global [%0], [%1], 16;\n" :: "r"(d), "l"(src));
}
__device__ __forceinline__ void cp_commit() {
    asm volatile("cp.async.commit_group;\n");
}
template <int N> __device__ __forceinline__ void cp_wait() {
    asm volatile("cp.async.wait_group %0;\n" :: "n"(N));
}

// ---------------------------------------------------------------------------
// Weight transpose+convert: Wt[out][in] f16 = W[in][out] fp32.
// ---------------------------------------------------------------------------
__global__ void __launch_bounds__(256) wconv_kernel(const float* __restrict__ Wq,
                                                    const float* __restrict__ Wk,
                                                    const float* __restrict__ Wv,
                                                    const float* __restrict__ Wn) {
    __shared__ float t[32][33];
    int w = blockIdx.z;
    const float* src = (w == 0) ? Wq : (w == 1) ? Wk : (w == 2) ? Wv : Wn;
    __half* dst = (w == 0) ? g_Wqt : (w == 1) ? g_Wkt : (w == 2) ? g_Wvt : g_Wnt;
    int c0 = blockIdx.x * 32, r0 = blockIdx.y * 32;
    int tx = threadIdx.x & 31, ty = threadIdx.x >> 5;
#pragma unroll
    for (int i = 0; i < 4; i++)
        t[ty + i * 8][tx] = src[(size_t)(r0 + ty + i * 8) * Cn + c0 + tx];
    __syncthreads();
#pragma unroll
    for (int i = 0; i < 4; i++)
        dst[(size_t)(c0 + ty + i * 8) * Cn + r0 + tx] = __float2half(t[tx][ty + i * 8]);
}

// ---------------------------------------------------------------------------
// GroupNorm: one block per (b, group); whole group tile in registers. -> f16
// ---------------------------------------------------------------------------
__global__ void __launch_bounds__(256) gn_kernel(const float* __restrict__ x) {
    int b = blockIdx.x >> 5, g = blockIdx.x & 31;
    size_t base = ((size_t)b * Cn + g * 16) * Sn;
    const float4* x4 = (const float4*)(x + base);
    int tid = threadIdx.x;

    float4 v[16];
    float s = 0.f, ss = 0.f;
#pragma unroll
    for (int i = 0; i < 16; i++) {
        v[i] = x4[tid + i * 256];
        s  += v[i].x + v[i].y + v[i].z + v[i].w;
        ss += v[i].x * v[i].x + v[i].y * v[i].y + v[i].z * v[i].z + v[i].w * v[i].w;
    }
    __shared__ float rs[256], rq[256];
    rs[tid] = s; rq[tid] = ss;
    __syncthreads();
    for (int off = 128; off; off >>= 1) {
        if (tid < off) { rs[tid] += rs[tid + off]; rq[tid] += rq[tid + off]; }
        __syncthreads();
    }
    const float invN = 1.f / 16384.f;
    float mean = rs[0] * invN;
    float var  = rq[0] * invN - mean * mean;
    float inv  = rsqrtf(var + 1e-5f);

    uint2* h2 = (uint2*)(g_hn + base);
#pragma unroll
    for (int i = 0; i < 16; i++) {
        __half2 p0 = __floats2half2_rn((v[i].x - mean) * inv, (v[i].y - mean) * inv);
        __half2 p1 = __floats2half2_rn((v[i].z - mean) * inv, (v[i].w - mean) * inv);
        uint2 u; u.x = *(unsigned*)&p0; u.y = *(unsigned*)&p1;
        h2[tid + i * 256] = u;
    }
}

// ---------------------------------------------------------------------------
// Fused QKV projection: ONE block computes Q, K and V for the same
// (s0, o0) tile, sharing the A tile and A fragments (3x MMAs per barrier,
// 1/3 the A traffic). Block 128(m=s) x 64(n=o), BK=32, 8 warps.
// out_w[b][s][o] = (sum_c hn[c][s]*W_w[c][o] + bias_w[o]) * qs_w
// ---------------------------------------------------------------------------
__global__ void __launch_bounds__(256) proj_kernel(const float* __restrict__ bq,
                                                   const float* __restrict__ bk,
                                                   const float* __restrict__ bv) {
    int b = blockIdx.z;
    int s0 = blockIdx.x * 128, o0 = blockIdx.y * 64;
    const __half* A = g_hn + (size_t)b * Cn * Sn;
    const __half* Wts[3] = {g_Wqt, g_Wkt, g_Wvt};

    __shared__ __align__(16) __half As[2][32][136];     // [k][m]
    __shared__ __align__(16) __half Bs[2][3][64][40];   // [w][n][k]

    int tid = threadIdx.x, lane = tid & 31, warp = tid >> 5;
    int wm = (warp & 3) * 32, wn = (warp >> 2) * 32;

    int ra = tid >> 3, ca = (tid & 7) * 16;  // As loader: 32 rows x 128 cols
    int rb = tid >> 2, cb = (tid & 3) * 8;   // Bs loader: 64 rows x 32 cols

    int mi = lane >> 3;
    int a_kr = (lane & 7) + ((mi >> 1) << 3);
    int a_mc = (mi & 1) << 3;

    // ldmatrix.x4 lane addressing for B ([n][k]):
    int q4 = lane >> 3, r8 = lane & 7;
    int b_ro = ((q4 >> 1) << 3) + r8, b_co = (q4 & 1) << 3;

    auto issue = [&](int c0, int st) {
        cp16(&As[st][ra][ca],     A + (size_t)(c0 + ra) * Sn + s0 + ca);
        cp16(&As[st][ra][ca + 8], A + (size_t)(c0 + ra) * Sn + s0 + ca + 8);
#pragma unroll
        for (int w = 0; w < 3; w++)
            cp16(&Bs[st][w][rb][cb], Wts[w] + (size_t)(o0 + rb) * Cn + c0 + cb);
        cp_commit();
    };
    issue(0, 0);
    issue(32, 1);

    unsigned acc[3][2][4][2] = {};
#pragma unroll 1
    for (int it = 0; it < 16; it++) {
        if (it < 14) cp_wait<1>(); else cp_wait<0>();
        __syncthreads();
        int st = it & 1;
#pragma unroll
        for (int kk = 0; kk < 32; kk += 16) {
            unsigned af[2][4];
#pragma unroll
            for (int im = 0; im < 2; im++) {
                unsigned addr = (unsigned)__cvta_generic_to_shared(
                    &As[st][kk + a_kr][wm + im * 16 + a_mc]);
                asm volatile(
                    "ldmatrix.sync.aligned.m8n8.x4.trans.shared.b16 {%0,%1,%2,%3},[%4];\n"
                    : "=r"(af[im][0]), "=r"(af[im][1]), "=r"(af[im][2]), "=r"(af[im][3])
                    : "r"(addr));
            }
#pragma unroll
            for (int w = 0; w < 3; w++) {
                unsigned bf[2][4];
#pragma unroll
                for (int jp = 0; jp < 2; jp++)
                    ldm_x4(bf[jp], &Bs[st][w][wn + jp * 16 + b_ro][kk + b_co]);
#pragma unroll
                for (int jp = 0; jp < 2; jp++)
#pragma unroll
                    for (int im = 0; im < 2; im++) {
                        mma_f16(acc[w][im][2 * jp],     af[im], bf[jp][0], bf[jp][1]);
                        mma_f16(acc[w][im][2 * jp + 1], af[im], bf[jp][2], bf[jp][3]);
                    }
            }
        }
        __syncthreads();
        if (it + 2 < 16) issue((it + 2) * 32, st);
    }

    int g = lane >> 2, t = lane & 3;
#pragma unroll
    for (int w = 0; w < 3; w++) {
        const float* bias = (w == 0) ? bq : (w == 1) ? bk : bv;
        __half* out = ((w == 0) ? g_Qt : (w == 1) ? g_Kt : g_Vt) + (size_t)b * Sn * Cn;
        const float qs = (w == 0) ? 0.04419417382415922f : 1.f;  // 512^-0.5 into Q
#pragma unroll
        for (int im = 0; im < 2; im++) {
            int m = s0 + wm + im * 16 + g;
#pragma unroll
            for (int jn = 0; jn < 4; jn++) {
                int n = o0 + wn + jn * 8 + 2 * t;
                float b0f = bias[n], b1f = bias[n + 1];
                float2 lo = __half22float2(*(__half2*)&acc[w][im][jn][0]);
                float2 hi = __half22float2(*(__half2*)&acc[w][im][jn][1]);
                __half2 v0 = __floats2half2_rn((lo.x + b0f) * qs, (lo.y + b1f) * qs);
                __half2 v1 = __floats2half2_rn((hi.x + b0f) * qs, (hi.y + b1f) * qs);
                *(unsigned*)(out + (size_t)m * Cn + n)       = *(unsigned*)&v0;
                *(unsigned*)(out + (size_t)(m + 8) * Cn + n) = *(unsigned*)&v1;
            }
        }
    }
}

// ---------------------------------------------------------------------------
// Scores + diag softmax; 512 threads, 4x4 warps, warp tile 32x32, f16 acc.
// BK=64 (8 iterations, half the barriers). Fragments via ldmatrix.x4 from
// [row][k] stride-72 smem (144B rows -> conflict-free ldmatrix phases).
// Block (jg, ig, b); each warp owns one 32x32 softmax group.
// ---------------------------------------------------------------------------
__global__ void __launch_bounds__(512) scores_kernel() {
    int b = blockIdx.z, ig = blockIdx.y, jg = blockIdx.x;
    const __half* Qb = g_Qt + (size_t)b * Sn * Cn;
    const __half* Kb = g_Kt + (size_t)b * Sn * Cn;

    __shared__ __align__(16) __half Qs[2][128][72];  // [m][k]
    __shared__ __align__(16) __half Ks[2][128][72];  // [n][k]

    int tid = threadIdx.x, lane = tid & 31, warp = tid >> 5;
    int ii = warp & 3, jj = warp >> 2;
    int wm = ii * 32, wn = jj * 32;

    int rr = tid >> 2, koff = (tid & 3) * 16;
    int s1 = (rr & 31) * 32 + ig * 4 + (rr >> 5);
    int s2 = (rr & 31) * 32 + jg * 4 + (rr >> 5);
    const __half* qrow = Qb + (size_t)s1 * Cn;
    const __half* krow = Kb + (size_t)s2 * Cn;

    // ldmatrix.x4 lane addressing
    int q4 = lane >> 3, r8 = lane & 7;
    int a_ro = ((q4 & 1) << 3) + r8, a_co = (q4 >> 1) << 3;   // A: m-rows, k-cols
    int b_ro = ((q4 >> 1) << 3) + r8, b_co = (q4 & 1) << 3;   // B: n-rows, k-cols

    auto issue = [&](int c0, int st) {
        cp16(&Qs[st][rr][koff],     qrow + c0 + koff);
        cp16(&Qs[st][rr][koff + 8], qrow + c0 + koff + 8);
        cp16(&Ks[st][rr][koff],     krow + c0 + koff);
        cp16(&Ks[st][rr][koff + 8], krow + c0 + koff + 8);
        cp_commit();
    };
    issue(0, 0);
    issue(64, 1);

    unsigned acc[2][4][2] = {};
#pragma unroll 1
    for (int it = 0; it < 8; it++) {
        if (it < 6) cp_wait<1>(); else cp_wait<0>();
        __syncthreads();
        int st = it & 1;
#pragma unroll
        for (int kk = 0; kk < 64; kk += 16) {
            unsigned af[2][4], bf[2][4];
#pragma unroll
            for (int im = 0; im < 2; im++)
                ldm_x4(af[im], &Qs[st][wm + im * 16 + a_ro][kk + a_co]);
#pragma unroll
            for (int jp = 0; jp < 2; jp++)
                ldm_x4(bf[jp], &Ks[st][wn + jp * 16 + b_ro][kk + b_co]);
#pragma unroll
            for (int jp = 0; jp < 2; jp++)
#pragma unroll
                for (int im = 0; im < 2; im++) {
                    mma_f16(acc[im][2 * jp],     af[im], bf[jp][0], bf[jp][1]);
                    mma_f16(acc[im][2 * jp + 1], af[im], bf[jp][2], bf[jp][3]);
                }
        }
        __syncthreads();
        if (it + 2 < 8) issue((it + 2) * 64, st);
    }

    // per-warp softmax over its 32x32 group (scale already folded into Q)
    float mx = -1e30f;
#pragma unroll
    for (int im = 0; im < 2; im++)
#pragma unroll
        for (int jn = 0; jn < 4; jn++)
#pragma unroll
            for (int r = 0; r < 2; r++) {
                float2 f = __half22float2(*(__half2*)&acc[im][jn][r]);
                mx = fmaxf(mx, fmaxf(f.x, f.y));
            }
#pragma unroll
    for (int off = 16; off; off >>= 1) mx = fmaxf(mx, __shfl_xor_sync(0xffffffffu, mx, off));

    float se = 0.f;
#pragma unroll
    for (int im = 0; im < 2; im++)
#pragma unroll
        for (int jn = 0; jn < 4; jn++)
#pragma unroll
            for (int r = 0; r < 2; r++) {
                float2 f = __half22float2(*(__half2*)&acc[im][jn][r]);
                se += __expf(f.x - mx) + __expf(f.y - mx);
            }
#pragma unroll
    for (int off = 16; off; off >>= 1) se += __shfl_xor_sync(0xffffffffu, se, off);

    // diag element at local (row = ig*4+ii, col = jg*4+jj)
    int rl = ig * 4 + ii, cl = jg * 4 + jj;
    int im_d = rl >> 4, rlow = rl & 15, reg_d = rlow >> 3, g_d = rlow & 7;
    int jn_d = cl >> 3, t_d = (cl & 7) >> 1, par = cl & 1;
    float cand = 0.f;
#pragma unroll
    for (int im = 0; im < 2; im++)
#pragma unroll
        for (int jn = 0; jn < 4; jn++)
#pragma unroll
            for (int r = 0; r < 2; r++)
                if (im == im_d && jn == jn_d && r == reg_d) {
                    float2 f = __half22float2(*(__half2*)&acc[im][jn][r]);
                    cand = par ? f.y : f.x;
                }
    float dv = __shfl_sync(0xffffffffu, cand, g_d * 4 + t_d);
    if (lane == 0) {
        int i = ig * 4 + ii, j = jg * 4 + jj;
        g_D[b * Sn + i * 32 + j] = __expf(dv - mx) / se;
    }
}

// ---------------------------------------------------------------------------
// Final GEMM, f16 acc, BK=64:
// out[b][c][s] = x + D[b][s]*(sum_o Wn[o][c]*Vt[b][s][o]) + bn[c]
// Block 128(m=c) x 64(n=s). All fragments via ldmatrix.x4.
// ---------------------------------------------------------------------------
__global__ void __launch_bounds__(256) final_kernel(const float* __restrict__ x,
                                                    const float* __restrict__ bn,
                                                    float* __restrict__ out) {
    int b = blockIdx.z, m0 = blockIdx.x * 128, n0 = blockIdx.y * 64;
    const __half* Bsrc = g_Vt + (size_t)b * Sn * Cn;

    __shared__ __align__(16) __half As[2][128][72];  // [m][k]
    __shared__ __align__(16) __half Bs[2][64][72];   // [n][k]
    __shared__ float Ds[64];

    int tid = threadIdx.x, lane = tid & 31, warp = tid >> 5;
    int wm = (warp & 3) * 32, wn = (warp >> 2) * 32;

    int ra = tid >> 1, ca = (tid & 1) * 32;   // As: 128 rows x 64 cols, 4 cp16
    int rb = tid >> 2, cb = (tid & 3) * 16;   // Bs: 64 rows x 64 cols, 2 cp16

    int q4 = lane >> 3, r8 = lane & 7;
    int a_ro = ((q4 & 1) << 3) + r8, a_co = (q4 >> 1) << 3;
    int b_ro = ((q4 >> 1) << 3) + r8, b_co = (q4 & 1) << 3;

    if (tid < 64) Ds[tid] = g_D[b * Sn + n0 + tid];

    auto issue = [&](int c0, int st) {
        const __half* ar = g_Wnt + (size_t)(m0 + ra) * Cn + c0 + ca;
        cp16(&As[st][ra][ca],      ar);
        cp16(&As[st][ra][ca + 8],  ar + 8);
        cp16(&As[st][ra][ca + 16], ar + 16);
        cp16(&As[st][ra][ca + 24], ar + 24);
        const __half* br = Bsrc + (size_t)(n0 + rb) * Cn + c0 + cb;
        cp16(&Bs[st][rb][cb],     br);
        cp16(&Bs[st][rb][cb + 8], br + 8);
        cp_commit();
    };
    issue(0, 0);
    issue(64, 1);

    unsigned acc[2][4][2] = {};
#pragma unroll 1
    for (int it = 0; it < 8; it++) {
        if (it < 6) cp_wait<1>(); else cp_wait<0>();
        __syncthreads();
        int st = it & 1;
#pragma unroll
        for (int kk = 0; kk < 64; kk += 16) {
            unsigned af[2][4], bf[2][4];
#pragma unroll
            for (int im = 0; im < 2; im++)
                ldm_x4(af[im], &As[st][wm + im * 16 + a_ro][kk + a_co]);
#pragma unroll
            for (int jp = 0; jp < 2; jp++)
                ldm_x4(bf[jp], &Bs[st][wn + jp * 16 + b_ro][kk + b_co]);
#pragma unroll
            for (int jp = 0; jp < 2; jp++)
#pragma unroll
                for (int im = 0; im < 2; im++) {
                    mma_f16(acc[im][2 * jp],     af[im], bf[jp][0], bf[jp][1]);
                    mma_f16(acc[im][2 * jp + 1], af[im], bf[jp][2], bf[jp][3]);
                }
        }
        __syncthreads();
        if (it + 2 < 8) issue((it + 2) * 64, st);
    }

    int g = lane >> 2, t = lane & 3;
#pragma unroll
    for (int im = 0; im < 2; im++) {
        int m = m0 + wm + im * 16 + g;
        float bb0 = bn[m], bb1 = bn[m + 8];
#pragma unroll
        for (int jn = 0; jn < 4; jn++) {
            int n = n0 + wn + jn * 8 + 2 * t;
            float d0 = Ds[n - n0], d1 = Ds[n - n0 + 1];
            float2 lo = __half22float2(*(__half2*)&acc[im][jn][0]);
            float2 hi = __half22float2(*(__half2*)&acc[im][jn][1]);
            size_t idx = ((size_t)b * Cn + m) * Sn + n;
            float2 xr = *(const float2*)(x + idx);
            float2 o0v = {xr.x + d0 * lo.x + bb0, xr.y + d1 * lo.y + bb0};
            *(float2*)(out + idx) = o0v;
            size_t idx2 = idx + 8 * (size_t)Sn;
            float2 xr2 = *(const float2*)(x + idx2);
            float2 o1v = {xr2.x + d0 * hi.x + bb1, xr2.y + d1 * hi.y + bb1};
            *(float2*)(out + idx2) = o1v;
        }
    }
}

// ---------------------------------------------------------------------------
extern "C" void kernel_launch(void* const* d_in, const int* in_sizes, int n_in,
                              void* d_out, int out_size) {
    const float* x  = (const float*)d_in[0];
    const float* Wq = (const float*)d_in[1];
    const float* bq = (const float*)d_in[2];
    const float* Wk = (const float*)d_in[3];
    const float* bk = (const float*)d_in[4];
    const float* Wv = (const float*)d_in[5];
    const float* bv = (const float*)d_in[6];
    const float* Wn = (const float*)d_in[7];
    const float* bn = (const float*)d_in[8];
    float* out = (float*)d_out;

    wconv_kernel<<<dim3(16, 16, 4), 256>>>(Wq, Wk, Wv, Wn);
    gn_kernel<<<Bn * 32, 256>>>(x);

    proj_kernel<<<dim3(8, 8, Bn), 256>>>(bq, bk, bv);

    scores_kernel<<<dim3(8, 8, Bn), 512>>>();

    final_kernel<<<dim3(Cn / 128, Sn / 64, Bn), 256>>>(x, bn, out);
}